// round 4
// baseline (speedup 1.0000x reference)
#include <cuda_runtime.h>
#include <cstdint>
#include <cstddef>

#define BATCH 128
#define RR    196
#define ENCD  2048
#define ATTD  512
#define DECD  512
#define EMBD  512
#define VOC   10000
#define TSTEPS 20

// ---------------- device scratch (static allocation only) ----------------
__device__ float g_att1[BATCH * RR * ATTD];        // 12.8M floats
__device__ float g_mean[BATCH * ENCD];
__device__ float g_state[BATCH * 1024];            // [h | c] per row
__device__ float g_hproj[BATCH * 4608];            // [att2 | fbeta_pre | hWhh]
__device__ float g_alpha[BATCH * RR];
__device__ float g_ctx[BATCH * ENCD];
__device__ float g_gadd[BATCH * 2048];
__device__ float g_gates[BATCH * 2048];
__device__ float g_E[BATCH * TSTEPS * EMBD];
__device__ float g_embproj[BATCH * TSTEPS * 2048];
__device__ float g_Wcat[4608 * 512];
__device__ float g_bcat[4608];
__device__ float g_bsum[2048];
__device__ float g_Winit[1024 * ENCD];
__device__ float g_binit[1024];

// ---------------- helpers ----------------
__device__ __forceinline__ float f2tf32(float x) {
    float r;
    asm("cvt.rna.tf32.f32 %0, %1;" : "=f"(r) : "f"(x));
    return r;
}

#define MMA_TF32(c, a, b0, b1)                                              \
    asm volatile(                                                           \
        "mma.sync.aligned.m16n8k8.row.col.f32.tf32.tf32.f32 "               \
        "{%0,%1,%2,%3}, {%4,%5,%6,%7}, {%8,%9}, {%0,%1,%2,%3};"             \
        : "+f"(c[0]), "+f"(c[1]), "+f"(c[2]), "+f"(c[3])                    \
        : "r"(a[0]), "r"(a[1]), "r"(a[2]), "r"(a[3]), "r"(b0), "r"(b1))

// C[M,N] = A[M,K] @ B[N,K]^T (+bias[N]) (+Csrc[M,N])
// PRECISE=true: fp32-faithful via tf32 hi/lo 3-pass. PRECISE=false: single tf32 pass.
template <bool PRECISE>
__global__ void gemm_tf32_kernel(const float* __restrict__ A, int lda,
                                 const float* __restrict__ Bm, int ldb,
                                 const float* __restrict__ bias,
                                 const float* __restrict__ Csrc, int ldsrc,
                                 float* __restrict__ C, int ldc,
                                 int M, int N, int K) {
    __shared__ float Ah[64][36];
    __shared__ float Bh[64][36];
    __shared__ float Al[PRECISE ? 64 : 1][36];
    __shared__ float Bl[PRECISE ? 64 : 1][36];

    const int tid = threadIdx.x;  // 128 threads
    const int m0 = blockIdx.y * 64;
    const int n0 = blockIdx.x * 64;

    const int warp = tid >> 5, lane = tid & 31;
    const int g = lane >> 2, tg = lane & 3;
    const int wm = (warp >> 1) * 32, wn = (warp & 1) * 32;

    float acc[2][4][4];
#pragma unroll
    for (int mi = 0; mi < 2; mi++)
#pragma unroll
        for (int ni = 0; ni < 4; ni++)
#pragma unroll
            for (int j = 0; j < 4; j++) acc[mi][ni][j] = 0.f;

    for (int kt = 0; kt < K; kt += 32) {
        if (kt) __syncthreads();
        // stage A and B tiles (64 rows x 32 k) with tf32 rounding (+ residual)
#pragma unroll
        for (int i = 0; i < 4; i++) {
            int q = tid + i * 128;       // 0..511
            int r = q >> 3;
            int kq = (q & 7) << 2;
            // A
            float4 v = make_float4(0.f, 0.f, 0.f, 0.f);
            int row = m0 + r;
            if (row < M) v = *(const float4*)(A + (size_t)row * lda + kt + kq);
            float4 h4;
            h4.x = f2tf32(v.x); h4.y = f2tf32(v.y); h4.z = f2tf32(v.z); h4.w = f2tf32(v.w);
            *(float4*)&Ah[r][kq] = h4;
            if (PRECISE) {
                float4 l4;
                l4.x = f2tf32(v.x - h4.x); l4.y = f2tf32(v.y - h4.y);
                l4.z = f2tf32(v.z - h4.z); l4.w = f2tf32(v.w - h4.w);
                *(float4*)&Al[r][kq] = l4;
            }
            // B
            float4 w = make_float4(0.f, 0.f, 0.f, 0.f);
            int rowb = n0 + r;
            if (rowb < N) w = *(const float4*)(Bm + (size_t)rowb * ldb + kt + kq);
            float4 hb;
            hb.x = f2tf32(w.x); hb.y = f2tf32(w.y); hb.z = f2tf32(w.z); hb.w = f2tf32(w.w);
            *(float4*)&Bh[r][kq] = hb;
            if (PRECISE) {
                float4 lb;
                lb.x = f2tf32(w.x - hb.x); lb.y = f2tf32(w.y - hb.y);
                lb.z = f2tf32(w.z - hb.z); lb.w = f2tf32(w.w - hb.w);
                *(float4*)&Bl[r][kq] = lb;
            }
        }
        __syncthreads();

#pragma unroll
        for (int ks = 0; ks < 4; ks++) {
            const int k0 = ks * 8;
            unsigned ah[2][4], al[2][4];
#pragma unroll
            for (int mi = 0; mi < 2; mi++) {
                int r = wm + mi * 16;
                ah[mi][0] = __float_as_uint(Ah[r + g][k0 + tg]);
                ah[mi][1] = __float_as_uint(Ah[r + g + 8][k0 + tg]);
                ah[mi][2] = __float_as_uint(Ah[r + g][k0 + tg + 4]);
                ah[mi][3] = __float_as_uint(Ah[r + g + 8][k0 + tg + 4]);
                if (PRECISE) {
                    al[mi][0] = __float_as_uint(Al[r + g][k0 + tg]);
                    al[mi][1] = __float_as_uint(Al[r + g + 8][k0 + tg]);
                    al[mi][2] = __float_as_uint(Al[r + g][k0 + tg + 4]);
                    al[mi][3] = __float_as_uint(Al[r + g + 8][k0 + tg + 4]);
                }
            }
#pragma unroll
            for (int ni = 0; ni < 4; ni++) {
                int cb = wn + ni * 8;
                unsigned bh0 = __float_as_uint(Bh[cb + g][k0 + tg]);
                unsigned bh1 = __float_as_uint(Bh[cb + g][k0 + tg + 4]);
#pragma unroll
                for (int mi = 0; mi < 2; mi++) MMA_TF32(acc[mi][ni], ah[mi], bh0, bh1);
                if (PRECISE) {
                    unsigned bl0 = __float_as_uint(Bl[cb + g][k0 + tg]);
                    unsigned bl1 = __float_as_uint(Bl[cb + g][k0 + tg + 4]);
#pragma unroll
                    for (int mi = 0; mi < 2; mi++) {
                        MMA_TF32(acc[mi][ni], al[mi], bh0, bh1);
                        MMA_TF32(acc[mi][ni], ah[mi], bl0, bl1);
                    }
                }
            }
        }
    }

    // epilogue
#pragma unroll
    for (int mi = 0; mi < 2; mi++) {
#pragma unroll
        for (int ni = 0; ni < 4; ni++) {
            int r0 = m0 + wm + mi * 16 + g;
            int c0 = n0 + wn + ni * 8 + tg * 2;
#pragma unroll
            for (int half = 0; half < 2; half++) {
                int rr = r0 + half * 8;
                if (rr >= M) continue;
#pragma unroll
                for (int j = 0; j < 2; j++) {
                    int cc = c0 + j;
                    if (cc >= N) continue;
                    float v = acc[mi][ni][half * 2 + j];
                    if (bias) v += bias[cc];
                    if (Csrc) v += Csrc[(size_t)rr * ldsrc + cc];
                    C[(size_t)rr * ldc + cc] = v;
                }
            }
        }
    }
}

// ---------------- small kernels ----------------
__global__ void bsum_kernel(float* __restrict__ out, const float* __restrict__ a,
                            const float* __restrict__ b) {
    int i = blockIdx.x * blockDim.x + threadIdx.x;
    if (i < 2048) out[i] = a[i] + b[i];
}

__global__ void gather_kernel(const int* __restrict__ cap, const float* __restrict__ table,
                              float* __restrict__ E) {
    int bt = blockIdx.x;            // 0..2559
    int b = bt / TSTEPS, tt = bt % TSTEPS;
    int idx = cap[b * (TSTEPS + 1) + tt];
    const float4* src = (const float4*)(table + (size_t)idx * EMBD);
    float4* dst = (float4*)(E + (size_t)bt * EMBD);
    dst[threadIdx.x] = src[threadIdx.x];  // 128 threads * float4 = 512 floats
}

__global__ void mean_kernel(const float* __restrict__ enc, float* __restrict__ mean) {
    int b = blockIdx.y;
    int e = blockIdx.x * 256 + threadIdx.x;
    const float* ep = enc + (size_t)b * RR * ENCD + e;
    float acc = 0.f;
#pragma unroll 4
    for (int r = 0; r < RR; r++) acc += ep[(size_t)r * ENCD];
    mean[b * ENCD + e] = acc * (1.f / (float)RR);
}

__global__ void attention_kernel(const float* __restrict__ att1,
                                 const float* __restrict__ hproj,
                                 const float* __restrict__ wfull,
                                 const float* __restrict__ bfull,
                                 float* __restrict__ alpha_out,
                                 float* __restrict__ out_alpha, int t) {
    int b = blockIdx.x;
    int tid = threadIdx.x;  // 256
    __shared__ float s_att2[512], s_wf[512], s_sc[RR], s_red[8];
    for (int i = tid; i < 512; i += 256) {
        s_att2[i] = hproj[b * 4608 + i];
        s_wf[i] = wfull[i];
    }
    __syncthreads();
    int warp = tid >> 5, lane = tid & 31;
    float bf = bfull[0];
    for (int r = warp; r < RR; r += 8) {
        const float* ap = att1 + ((size_t)(b * RR + r)) * 512;
        float s = 0.f;
#pragma unroll 4
        for (int a = lane; a < 512; a += 32) {
            float v = ap[a] + s_att2[a];
            s += fmaxf(v, 0.f) * s_wf[a];
        }
#pragma unroll
        for (int o = 16; o; o >>= 1) s += __shfl_xor_sync(0xffffffffu, s, o);
        if (lane == 0) s_sc[r] = s + bf;
    }
    __syncthreads();
    // softmax over RR
    float m = -1e30f;
    for (int i = tid; i < RR; i += 256) m = fmaxf(m, s_sc[i]);
#pragma unroll
    for (int o = 16; o; o >>= 1) m = fmaxf(m, __shfl_xor_sync(0xffffffffu, m, o));
    if (lane == 0) s_red[warp] = m;
    __syncthreads();
    m = s_red[0];
#pragma unroll
    for (int w = 1; w < 8; w++) m = fmaxf(m, s_red[w]);
    __syncthreads();
    float sum = 0.f;
    for (int i = tid; i < RR; i += 256) {
        float e = expf(s_sc[i] - m);
        s_sc[i] = e;
        sum += e;
    }
#pragma unroll
    for (int o = 16; o; o >>= 1) sum += __shfl_xor_sync(0xffffffffu, sum, o);
    if (lane == 0) s_red[warp] = sum;
    __syncthreads();
    sum = 0.f;
#pragma unroll
    for (int w = 0; w < 8; w++) sum += s_red[w];
    float inv = 1.f / sum;
    for (int i = tid; i < RR; i += 256) {
        float a = s_sc[i] * inv;
        alpha_out[b * RR + i] = a;
        out_alpha[((size_t)b * TSTEPS + t) * RR + i] = a;
    }
}

__global__ void ctx_kernel(const float* __restrict__ enc, const float* __restrict__ alpha,
                           const float* __restrict__ hproj, const float* __restrict__ embproj,
                           float* __restrict__ ctx, float* __restrict__ gadd, int t) {
    int b = blockIdx.y;
    int e = blockIdx.x * 256 + threadIdx.x;
    __shared__ float s_a[RR];
    for (int i = threadIdx.x; i < RR; i += 256) s_a[i] = alpha[b * RR + i];
    __syncthreads();
    const float* ep = enc + (size_t)b * RR * ENCD + e;
    float acc = 0.f;
#pragma unroll 4
    for (int r = 0; r < RR; r++) acc += s_a[r] * ep[(size_t)r * ENCD];
    float gpre = hproj[b * 4608 + 512 + e];
    float gate = 1.f / (1.f + expf(-gpre));
    ctx[b * ENCD + e] = gate * acc;
    gadd[b * 2048 + e] = embproj[((size_t)b * TSTEPS + t) * 2048 + e] + hproj[b * 4608 + 2560 + e];
}

__global__ void lstm_kernel(const float* __restrict__ gates, float* __restrict__ state) {
    int b = blockIdx.x, d = threadIdx.x;  // 512 threads
    const float* gt = gates + b * 2048;
    float i_ = 1.f / (1.f + expf(-gt[d]));
    float f_ = 1.f / (1.f + expf(-gt[512 + d]));
    float g_ = tanhf(gt[1024 + d]);
    float o_ = 1.f / (1.f + expf(-gt[1536 + d]));
    float c = state[b * 1024 + 512 + d];
    float cn = f_ * c + i_ * g_;
    float hn = o_ * tanhf(cn);
    state[b * 1024 + d] = hn;
    state[b * 1024 + 512 + d] = cn;
}

// ---------------- host ----------------
static float* symaddr(const void* sym) {
    void* p = nullptr;
    cudaGetSymbolAddress(&p, sym);
    return (float*)p;
}

static void launch_gemm(bool precise, const float* A, int lda, const float* B, int ldb,
                        const float* bias, const float* Csrc, int ldsrc, float* C, int ldc,
                        int M, int N, int K) {
    dim3 grid((N + 63) / 64, (M + 63) / 64);
    if (precise)
        gemm_tf32_kernel<true><<<grid, 128>>>(A, lda, B, ldb, bias, Csrc, ldsrc, C, ldc, M, N, K);
    else
        gemm_tf32_kernel<false><<<grid, 128>>>(A, lda, B, ldb, bias, Csrc, ldsrc, C, ldc, M, N, K);
}

extern "C" void kernel_launch(void* const* d_in, const int* in_sizes, int n_in,
                              void* d_out, int out_size) {
    const float* enc       = (const float*)d_in[0];
    const int*   captions  = (const int*)d_in[1];
    const float* W_enc_att = (const float*)d_in[2];
    const float* b_enc_att = (const float*)d_in[3];
    const float* W_dec_att = (const float*)d_in[4];
    const float* b_dec_att = (const float*)d_in[5];
    const float* W_full    = (const float*)d_in[6];
    const float* b_full    = (const float*)d_in[7];
    const float* emb_table = (const float*)d_in[8];
    const float* W_ih      = (const float*)d_in[9];
    const float* W_hh      = (const float*)d_in[10];
    const float* b_ih      = (const float*)d_in[11];
    const float* b_hh      = (const float*)d_in[12];
    const float* W_init_h  = (const float*)d_in[13];
    const float* b_init_h  = (const float*)d_in[14];
    const float* W_init_c  = (const float*)d_in[15];
    const float* b_init_c  = (const float*)d_in[16];
    const float* W_fbeta   = (const float*)d_in[17];
    const float* b_fbeta   = (const float*)d_in[18];
    const float* W_fc      = (const float*)d_in[19];
    const float* b_fc      = (const float*)d_in[20];

    float* out_pred  = (float*)d_out;
    float* out_alpha = out_pred + (size_t)BATCH * TSTEPS * VOC;

    float* att1   = symaddr(g_att1);
    float* meanb  = symaddr(g_mean);
    float* state  = symaddr(g_state);
    float* hproj  = symaddr(g_hproj);
    float* alpha  = symaddr(g_alpha);
    float* ctx    = symaddr(g_ctx);
    float* gadd   = symaddr(g_gadd);
    float* gates  = symaddr(g_gates);
    float* E      = symaddr(g_E);
    float* embprj = symaddr(g_embproj);
    float* Wcat   = symaddr(g_Wcat);
    float* bcat   = symaddr(g_bcat);
    float* bsum   = symaddr(g_bsum);
    float* Winit  = symaddr(g_Winit);
    float* binit  = symaddr(g_binit);

    // ---- prologue: weight concats (D2D copies are graph-capturable) ----
    cudaMemcpyAsync(Wcat, W_dec_att, (size_t)512 * 512 * 4, cudaMemcpyDeviceToDevice, 0);
    cudaMemcpyAsync(Wcat + 512 * 512, W_fbeta, (size_t)2048 * 512 * 4, cudaMemcpyDeviceToDevice, 0);
    cudaMemcpyAsync(Wcat + 2560 * 512, W_hh, (size_t)2048 * 512 * 4, cudaMemcpyDeviceToDevice, 0);
    cudaMemcpyAsync(bcat, b_dec_att, 512 * 4, cudaMemcpyDeviceToDevice, 0);
    cudaMemcpyAsync(bcat + 512, b_fbeta, 2048 * 4, cudaMemcpyDeviceToDevice, 0);
    cudaMemsetAsync(bcat + 2560, 0, 2048 * 4, 0);
    cudaMemcpyAsync(Winit, W_init_h, (size_t)512 * 2048 * 4, cudaMemcpyDeviceToDevice, 0);
    cudaMemcpyAsync(Winit + (size_t)512 * 2048, W_init_c, (size_t)512 * 2048 * 4,
                    cudaMemcpyDeviceToDevice, 0);
    cudaMemcpyAsync(binit, b_init_h, 512 * 4, cudaMemcpyDeviceToDevice, 0);
    cudaMemcpyAsync(binit + 512, b_init_c, 512 * 4, cudaMemcpyDeviceToDevice, 0);

    bsum_kernel<<<8, 256>>>(bsum, b_ih, b_hh);
    mean_kernel<<<dim3(8, BATCH), 256>>>(enc, meanb);
    // state = [h0 | c0] = mean @ [W_init_h; W_init_c]^T + [b_init_h; b_init_c]
    launch_gemm(true, meanb, ENCD, Winit, ENCD, binit, nullptr, 0, state, 1024, BATCH, 1024, ENCD);
    gather_kernel<<<BATCH * TSTEPS, 128>>>(captions, emb_table, E);
    // emb projection for all timesteps: E @ W_ih[:, :512]^T + (b_ih + b_hh)
    launch_gemm(false, E, EMBD, W_ih, EMBD + ENCD, bsum, nullptr, 0, embprj, 2048,
                BATCH * TSTEPS, 2048, EMBD);
    // att1 = enc @ W_enc_att^T + b_enc_att   (25088 x 512, K=2048)
    launch_gemm(false, enc, ENCD, W_enc_att, ENCD, b_enc_att, nullptr, 0, att1, ATTD,
                BATCH * RR, ATTD, ENCD);

    // ---- recurrence ----
    for (int t = 0; t < TSTEPS; t++) {
        // hproj = h @ [W_dec_att; W_fbeta; W_hh]^T + [b_dec_att; b_fbeta; 0]
        launch_gemm(true, state, 1024, Wcat, 512, bcat, nullptr, 0, hproj, 4608,
                    BATCH, 4608, DECD);
        attention_kernel<<<BATCH, 256>>>(att1, hproj, W_full, b_full, alpha, out_alpha, t);
        ctx_kernel<<<dim3(8, BATCH), 256>>>(enc, alpha, hproj, embprj, ctx, gadd, t);
        // gates = ctx @ W_ih[:, 512:]^T + (embproj_t + hWhh)   (bias folded in embproj)
        launch_gemm(true, ctx, ENCD, W_ih + 512, EMBD + ENCD, nullptr, gadd, 2048, gates, 2048,
                    BATCH, 2048, ENCD);
        lstm_kernel<<<BATCH, 512>>>(gates, state);
        // pred = h_new @ W_fc^T + b_fc -> out[:, t, :]
        launch_gemm(true, state, 1024, W_fc, DECD, b_fc, nullptr, 0, out_pred + (size_t)t * VOC,
                    TSTEPS * VOC, BATCH, VOC, DECD);
    }
}

// round 5
// speedup vs baseline: 2.5590x; 2.5590x over previous
#include <cuda_runtime.h>
#include <cstdint>
#include <cstddef>

#define BATCH 128
#define RR    196
#define ENCD  2048
#define ATTD  512
#define DECD  512
#define EMBD  512
#define VOC   10000
#define TSTEPS 20

// ---------------- device scratch (static allocation only) ----------------
__device__ float g_att1[BATCH * RR * ATTD];
__device__ float g_mean[BATCH * ENCD];
__device__ float g_state[BATCH * 1024];            // [h | c]
__device__ float g_hproj[BATCH * 4608];            // [att2 | fbeta_pre | hWhh]
__device__ float g_alpha[BATCH * RR];
__device__ float g_ctx[BATCH * ENCD];
__device__ float g_gadd[BATCH * 2048];
__device__ float g_gpart[4 * BATCH * 2048];        // split-K partials for gates
__device__ float g_H[BATCH * TSTEPS * DECD];       // all h_t, row = b*TSTEPS+t
__device__ float g_E[BATCH * TSTEPS * EMBD];
__device__ float g_embproj[BATCH * TSTEPS * 2048];
__device__ float g_Wcat[4608 * 512];
__device__ float g_bcat[4608];
__device__ float g_bsum[2048];
__device__ float g_Winit[1024 * ENCD];
__device__ float g_binit[1024];

// ---------------- helpers ----------------
__device__ __forceinline__ float f2tf32(float x) {
    float r;
    asm("cvt.rna.tf32.f32 %0, %1;" : "=f"(r) : "f"(x));
    return r;
}

#define MMA_TF32(c, a, b0, b1)                                              \
    asm volatile(                                                           \
        "mma.sync.aligned.m16n8k8.row.col.f32.tf32.tf32.f32 "               \
        "{%0,%1,%2,%3}, {%4,%5,%6,%7}, {%8,%9}, {%0,%1,%2,%3};"             \
        : "+f"(c[0]), "+f"(c[1]), "+f"(c[2]), "+f"(c[3])                    \
        : "r"(a[0]), "r"(a[1]), "r"(a[2]), "r"(a[3]), "r"(b0), "r"(b1))

__device__ __forceinline__ void cp_async16(uint32_t saddr, const void* gptr, int src_bytes) {
    asm volatile("cp.async.cg.shared.global [%0], [%1], 16, %2;\n"
                 :: "r"(saddr), "l"(gptr), "r"(src_bytes));
}
__device__ __forceinline__ void cp_commit() { asm volatile("cp.async.commit_group;\n"); }

// ---------------- pipelined tf32 GEMM ----------------
// C[M,N] = A[M,K*gz] slice z @ B^T (+bias) (+Csrc) ; M multiple of 128.
// Tiles: BM=128, BN=64, BK=32. 256 threads, cp.async double buffer.
// PRECISE: 3-pass hi/lo split (hi = mantissa-truncated fp32, lo = exact residual).
#define SROW 36
#define STAGE (128 * SROW + 64 * SROW)   // 6912 floats

template <bool PRECISE>
__global__ void __launch_bounds__(256) gemm_pipe(
    const float* __restrict__ A, int lda,
    const float* __restrict__ Bm, int ldb,
    const float* __restrict__ bias,
    const float* __restrict__ Csrc, int ldsrc,
    float* __restrict__ Cbase, int ldc, size_t zstride,
    int N, int K) {
    extern __shared__ float smem[];
    const int tid = threadIdx.x;
    const int m0 = blockIdx.y * 128;
    const int n0 = blockIdx.x * 64;
    const int Koff = blockIdx.z * K;
    float* C = Cbase + (size_t)blockIdx.z * zstride;
    const bool final_z = (gridDim.z == 1);

    const int warp = tid >> 5, lane = tid & 31;
    const int g = lane >> 2, tg = lane & 3;
    const int wm = (warp >> 1) * 32;   // 4 warps along M
    const int wn = (warp & 1) * 32;    // 2 warps along N

    float acc[2][4][4];
#pragma unroll
    for (int mi = 0; mi < 2; mi++)
#pragma unroll
        for (int ni = 0; ni < 4; ni++)
#pragma unroll
            for (int j = 0; j < 4; j++) acc[mi][ni][j] = 0.f;

    const int ntiles = K >> 5;

    // stage loader
    auto load_stage = [&](int buf, int kt) {
        float* sA = smem + buf * STAGE;
        float* sB = sA + 128 * SROW;
        const int kb = Koff + kt;
#pragma unroll
        for (int i = 0; i < 4; i++) {
            int idx = tid + i * 256;          // 0..1023
            int row = idx >> 3;
            int q = (idx & 7) << 2;
            uint32_t d = (uint32_t)__cvta_generic_to_shared(sA + row * SROW + q);
            cp_async16(d, A + (size_t)(m0 + row) * lda + kb + q, 16);
        }
#pragma unroll
        for (int i = 0; i < 2; i++) {
            int idx = tid + i * 256;          // 0..511
            int row = idx >> 3;
            int q = (idx & 7) << 2;
            int nr = n0 + row;
            int ok = (nr < N);
            if (!ok) nr = N - 1;
            uint32_t d = (uint32_t)__cvta_generic_to_shared(sB + row * SROW + q);
            cp_async16(d, Bm + (size_t)nr * ldb + kb + q, ok ? 16 : 0);
        }
        cp_commit();
    };

    load_stage(0, 0);

    for (int kt = 0; kt < ntiles; kt++) {
        if (kt + 1 < ntiles) {
            load_stage((kt + 1) & 1, (kt + 1) << 5);
            asm volatile("cp.async.wait_group 1;\n");
        } else {
            asm volatile("cp.async.wait_group 0;\n");
        }
        __syncthreads();

        const float* sA = smem + (kt & 1) * STAGE;
        const float* sB = sA + 128 * SROW;

#pragma unroll
        for (int ks = 0; ks < 4; ks++) {
            const int k0 = ks * 8;
            unsigned ah[2][4], al[2][4];
#pragma unroll
            for (int mi = 0; mi < 2; mi++) {
                int r = wm + mi * 16;
#pragma unroll
                for (int e = 0; e < 4; e++) {
                    int rr = r + g + ((e & 1) ? 8 : 0);
                    int kk = k0 + tg + ((e & 2) ? 4 : 0);
                    float v = sA[rr * SROW + kk];
                    if (PRECISE) {
                        unsigned hb = __float_as_uint(v) & 0xffffe000u;
                        ah[mi][e] = hb;
                        al[mi][e] = __float_as_uint(v - __uint_as_float(hb));
                    } else {
                        ah[mi][e] = __float_as_uint(f2tf32(v));
                    }
                }
            }
#pragma unroll
            for (int ni = 0; ni < 4; ni++) {
                int cb = wn + ni * 8;
                float v0 = sB[(cb + g) * SROW + k0 + tg];
                float v1 = sB[(cb + g) * SROW + k0 + tg + 4];
                unsigned bh0, bh1, bl0, bl1;
                if (PRECISE) {
                    bh0 = __float_as_uint(v0) & 0xffffe000u;
                    bh1 = __float_as_uint(v1) & 0xffffe000u;
                    bl0 = __float_as_uint(v0 - __uint_as_float(bh0));
                    bl1 = __float_as_uint(v1 - __uint_as_float(bh1));
                } else {
                    bh0 = __float_as_uint(f2tf32(v0));
                    bh1 = __float_as_uint(f2tf32(v1));
                }
#pragma unroll
                for (int mi = 0; mi < 2; mi++) {
                    MMA_TF32(acc[mi][ni], ah[mi], bh0, bh1);
                    if (PRECISE) {
                        MMA_TF32(acc[mi][ni], al[mi], bh0, bh1);
                        MMA_TF32(acc[mi][ni], ah[mi], bl0, bl1);
                    }
                }
            }
        }
        __syncthreads();
    }

    // epilogue
#pragma unroll
    for (int mi = 0; mi < 2; mi++) {
#pragma unroll
        for (int ni = 0; ni < 4; ni++) {
            int r0 = m0 + wm + mi * 16 + g;
            int c0 = n0 + wn + ni * 8 + tg * 2;
#pragma unroll
            for (int half = 0; half < 2; half++) {
                int rr = r0 + half * 8;
#pragma unroll
                for (int j = 0; j < 2; j++) {
                    int cc = c0 + j;
                    if (cc >= N) continue;
                    float v = acc[mi][ni][half * 2 + j];
                    if (final_z) {
                        if (bias) v += bias[cc];
                        if (Csrc) v += Csrc[(size_t)rr * ldsrc + cc];
                    }
                    C[(size_t)rr * ldc + cc] = v;
                }
            }
        }
    }
}

// ---------------- small kernels ----------------
__global__ void bsum_kernel(float* __restrict__ out, const float* __restrict__ a,
                            const float* __restrict__ b) {
    int i = blockIdx.x * blockDim.x + threadIdx.x;
    if (i < 2048) out[i] = a[i] + b[i];
}

__global__ void gather_kernel(const int* __restrict__ cap, const float* __restrict__ table,
                              float* __restrict__ E) {
    int bt = blockIdx.x;
    int b = bt / TSTEPS, tt = bt % TSTEPS;
    int idx = cap[b * (TSTEPS + 1) + tt];
    const float4* src = (const float4*)(table + (size_t)idx * EMBD);
    float4* dst = (float4*)(E + (size_t)bt * EMBD);
    dst[threadIdx.x] = src[threadIdx.x];
}

__global__ void mean_kernel(const float* __restrict__ enc, float* __restrict__ mean) {
    int b = blockIdx.y;
    int e = blockIdx.x * 256 + threadIdx.x;
    const float* ep = enc + (size_t)b * RR * ENCD + e;
    float acc = 0.f;
#pragma unroll 4
    for (int r = 0; r < RR; r++) acc += ep[(size_t)r * ENCD];
    mean[b * ENCD + e] = acc * (1.f / (float)RR);
}

__global__ void __launch_bounds__(512) attention_kernel(
    const float* __restrict__ att1, const float* __restrict__ hproj,
    const float* __restrict__ wfull, const float* __restrict__ bfull,
    float* __restrict__ alpha_out, float* __restrict__ out_alpha, int t) {
    int b = blockIdx.x;
    int tid = threadIdx.x;  // 512
    __shared__ float s_att2[512], s_wf[512], s_sc[RR], s_red[16];
    s_att2[tid] = hproj[b * 4608 + tid];
    s_wf[tid] = wfull[tid];
    __syncthreads();
    int warp = tid >> 5, lane = tid & 31;
    float bf = bfull[0];
    for (int r = warp; r < RR; r += 16) {
        const float* ap = att1 + ((size_t)(b * RR + r)) * 512;
        float s = 0.f;
#pragma unroll 4
        for (int a = lane; a < 512; a += 32) {
            float v = ap[a] + s_att2[a];
            s += fmaxf(v, 0.f) * s_wf[a];
        }
#pragma unroll
        for (int o = 16; o; o >>= 1) s += __shfl_xor_sync(0xffffffffu, s, o);
        if (lane == 0) s_sc[r] = s + bf;
    }
    __syncthreads();
    float m = -1e30f;
    for (int i = tid; i < RR; i += 512) m = fmaxf(m, s_sc[i]);
#pragma unroll
    for (int o = 16; o; o >>= 1) m = fmaxf(m, __shfl_xor_sync(0xffffffffu, m, o));
    if (lane == 0) s_red[warp] = m;
    __syncthreads();
    m = s_red[0];
#pragma unroll
    for (int w = 1; w < 16; w++) m = fmaxf(m, s_red[w]);
    __syncthreads();
    float sum = 0.f;
    for (int i = tid; i < RR; i += 512) {
        float e = expf(s_sc[i] - m);
        s_sc[i] = e;
        sum += e;
    }
#pragma unroll
    for (int o = 16; o; o >>= 1) sum += __shfl_xor_sync(0xffffffffu, sum, o);
    if (lane == 0) s_red[warp] = sum;
    __syncthreads();
    sum = 0.f;
#pragma unroll
    for (int w = 0; w < 16; w++) sum += s_red[w];
    float inv = 1.f / sum;
    for (int i = tid; i < RR; i += 512) {
        float a = s_sc[i] * inv;
        alpha_out[b * RR + i] = a;
        out_alpha[((size_t)b * TSTEPS + t) * RR + i] = a;
    }
}

__global__ void ctx_kernel(const float* __restrict__ enc, const float* __restrict__ alpha,
                           const float* __restrict__ hproj, const float* __restrict__ embproj,
                           float* __restrict__ ctx, float* __restrict__ gadd, int t) {
    int b = blockIdx.y;
    int e = blockIdx.x * 256 + threadIdx.x;
    __shared__ float s_a[RR];
    for (int i = threadIdx.x; i < RR; i += 256) s_a[i] = alpha[b * RR + i];
    __syncthreads();
    const float* ep = enc + (size_t)b * RR * ENCD + e;
    float acc = 0.f;
#pragma unroll 4
    for (int r = 0; r < RR; r++) acc += s_a[r] * ep[(size_t)r * ENCD];
    float gpre = hproj[b * 4608 + 512 + e];
    float gate = 1.f / (1.f + expf(-gpre));
    ctx[b * ENCD + e] = gate * acc;
    gadd[b * 2048 + e] = embproj[((size_t)b * TSTEPS + t) * 2048 + e] + hproj[b * 4608 + 2560 + e];
}

// sums 4 split-K partials + gadd, does LSTM pointwise, writes h to state AND g_H[t]
__global__ void lstm_kernel(const float* __restrict__ gpart, const float* __restrict__ gadd,
                            float* __restrict__ state, float* __restrict__ Hout, int t) {
    int b = blockIdx.x, d = threadIdx.x;  // 512 threads
    float gt[4];
#pragma unroll
    for (int q = 0; q < 4; q++) {
        int j = b * 2048 + q * 512 + d;
        float s = gadd[j];
#pragma unroll
        for (int z = 0; z < 4; z++) s += gpart[z * BATCH * 2048 + j];
        gt[q] = s;
    }
    float i_ = 1.f / (1.f + expf(-gt[0]));
    float f_ = 1.f / (1.f + expf(-gt[1]));
    float g_ = tanhf(gt[2]);
    float o_ = 1.f / (1.f + expf(-gt[3]));
    float c = state[b * 1024 + 512 + d];
    float cn = f_ * c + i_ * g_;
    float hn = o_ * tanhf(cn);
    state[b * 1024 + d] = hn;
    state[b * 1024 + 512 + d] = cn;
    Hout[((size_t)b * TSTEPS + t) * DECD + d] = hn;
}

// ---------------- host ----------------
static float* symaddr(const void* sym) {
    void* p = nullptr;
    cudaGetSymbolAddress(&p, sym);
    return (float*)p;
}

static const int GEMM_SMEM = 2 * STAGE * 4;  // 55296 bytes

static void launch_gemm(bool precise, const float* A, int lda, const float* B, int ldb,
                        const float* bias, const float* Csrc, int ldsrc, float* C, int ldc,
                        size_t zstride, int M, int N, int K, int zsplit) {
    dim3 grid((N + 63) / 64, M / 128, zsplit);
    if (precise)
        gemm_pipe<true><<<grid, 256, GEMM_SMEM>>>(A, lda, B, ldb, bias, Csrc, ldsrc, C, ldc,
                                                  zstride, N, K / zsplit);
    else
        gemm_pipe<false><<<grid, 256, GEMM_SMEM>>>(A, lda, B, ldb, bias, Csrc, ldsrc, C, ldc,
                                                   zstride, N, K / zsplit);
}

extern "C" void kernel_launch(void* const* d_in, const int* in_sizes, int n_in,
                              void* d_out, int out_size) {
    const float* enc       = (const float*)d_in[0];
    const int*   captions  = (const int*)d_in[1];
    const float* W_enc_att = (const float*)d_in[2];
    const float* b_enc_att = (const float*)d_in[3];
    const float* W_dec_att = (const float*)d_in[4];
    const float* b_dec_att = (const float*)d_in[5];
    const float* W_full    = (const float*)d_in[6];
    const float* b_full    = (const float*)d_in[7];
    const float* emb_table = (const float*)d_in[8];
    const float* W_ih      = (const float*)d_in[9];
    const float* W_hh      = (const float*)d_in[10];
    const float* b_ih      = (const float*)d_in[11];
    const float* b_hh      = (const float*)d_in[12];
    const float* W_init_h  = (const float*)d_in[13];
    const float* b_init_h  = (const float*)d_in[14];
    const float* W_init_c  = (const float*)d_in[15];
    const float* b_init_c  = (const float*)d_in[16];
    const float* W_fbeta   = (const float*)d_in[17];
    const float* b_fbeta   = (const float*)d_in[18];
    const float* W_fc      = (const float*)d_in[19];
    const float* b_fc      = (const float*)d_in[20];

    float* out_pred  = (float*)d_out;
    float* out_alpha = out_pred + (size_t)BATCH * TSTEPS * VOC;

    float* att1   = symaddr(g_att1);
    float* meanb  = symaddr(g_mean);
    float* state  = symaddr(g_state);
    float* hproj  = symaddr(g_hproj);
    float* alpha  = symaddr(g_alpha);
    float* ctx    = symaddr(g_ctx);
    float* gadd   = symaddr(g_gadd);
    float* gpart  = symaddr(g_gpart);
    float* Hbuf   = symaddr(g_H);
    float* E      = symaddr(g_E);
    float* embprj = symaddr(g_embproj);
    float* Wcat   = symaddr(g_Wcat);
    float* bcat   = symaddr(g_bcat);
    float* bsum   = symaddr(g_bsum);
    float* Winit  = symaddr(g_Winit);
    float* binit  = symaddr(g_binit);

    cudaFuncSetAttribute(gemm_pipe<true>, cudaFuncAttributeMaxDynamicSharedMemorySize, GEMM_SMEM);
    cudaFuncSetAttribute(gemm_pipe<false>, cudaFuncAttributeMaxDynamicSharedMemorySize, GEMM_SMEM);

    // ---- prologue: weight concats ----
    cudaMemcpyAsync(Wcat, W_dec_att, (size_t)512 * 512 * 4, cudaMemcpyDeviceToDevice, 0);
    cudaMemcpyAsync(Wcat + 512 * 512, W_fbeta, (size_t)2048 * 512 * 4, cudaMemcpyDeviceToDevice, 0);
    cudaMemcpyAsync(Wcat + 2560 * 512, W_hh, (size_t)2048 * 512 * 4, cudaMemcpyDeviceToDevice, 0);
    cudaMemcpyAsync(bcat, b_dec_att, 512 * 4, cudaMemcpyDeviceToDevice, 0);
    cudaMemcpyAsync(bcat + 512, b_fbeta, 2048 * 4, cudaMemcpyDeviceToDevice, 0);
    cudaMemsetAsync(bcat + 2560, 0, 2048 * 4, 0);
    cudaMemcpyAsync(Winit, W_init_h, (size_t)512 * 2048 * 4, cudaMemcpyDeviceToDevice, 0);
    cudaMemcpyAsync(Winit + (size_t)512 * 2048, W_init_c, (size_t)512 * 2048 * 4,
                    cudaMemcpyDeviceToDevice, 0);
    cudaMemcpyAsync(binit, b_init_h, 512 * 4, cudaMemcpyDeviceToDevice, 0);
    cudaMemcpyAsync(binit + 512, b_init_c, 512 * 4, cudaMemcpyDeviceToDevice, 0);

    bsum_kernel<<<8, 256>>>(bsum, b_ih, b_hh);
    mean_kernel<<<dim3(8, BATCH), 256>>>(enc, meanb);
    // state = mean @ [W_init_h; W_init_c]^T + [b_init_h; b_init_c]
    launch_gemm(true, meanb, ENCD, Winit, ENCD, binit, nullptr, 0, state, 1024, 0,
                BATCH, 1024, ENCD, 1);
    gather_kernel<<<BATCH * TSTEPS, 128>>>(captions, emb_table, E);
    // embproj (all t): E @ W_ih[:, :512]^T + (b_ih + b_hh)
    launch_gemm(false, E, EMBD, W_ih, EMBD + ENCD, bsum, nullptr, 0, embprj, 2048, 0,
                BATCH * TSTEPS, 2048, EMBD, 1);
    // att1 = enc @ W_enc_att^T + b_enc_att
    launch_gemm(false, enc, ENCD, W_enc_att, ENCD, b_enc_att, nullptr, 0, att1, ATTD, 0,
                BATCH * RR, ATTD, ENCD, 1);

    // ---- recurrence (fc GEMM hoisted out of the loop) ----
    for (int t = 0; t < TSTEPS; t++) {
        // hproj = h @ [W_dec_att; W_fbeta; W_hh]^T + [b_dec_att; b_fbeta; 0]
        launch_gemm(true, state, 1024, Wcat, 512, bcat, nullptr, 0, hproj, 4608, 0,
                    BATCH, 4608, DECD, 1);
        attention_kernel<<<BATCH, 512>>>(att1, hproj, W_full, b_full, alpha, out_alpha, t);
        ctx_kernel<<<dim3(8, BATCH), 256>>>(enc, alpha, hproj, embprj, ctx, gadd, t);
        // gates partials = ctx @ W_ih[:, 512:]^T   (split-K = 4)
        launch_gemm(true, ctx, ENCD, W_ih + 512, EMBD + ENCD, nullptr, nullptr, 0, gpart, 2048,
                    (size_t)BATCH * 2048, BATCH, 2048, ENCD, 4);
        lstm_kernel<<<BATCH, 512>>>(gpart, gadd, state, Hbuf, t);
    }

    // ---- batched fc: preds[b,t,:] = h_t @ W_fc^T + b_fc ----
    launch_gemm(true, Hbuf, DECD, W_fc, DECD, b_fc, nullptr, 0, out_pred, VOC, 0,
                BATCH * TSTEPS, VOC, DECD, 1);
}

// round 6
// speedup vs baseline: 2.7605x; 1.0787x over previous
#include <cuda_runtime.h>
#include <cuda_bf16.h>
#include <cstdint>
#include <cstddef>

#define BATCH 128
#define RR    196
#define ENCD  2048
#define ATTD  512
#define DECD  512
#define EMBD  512
#define VOC   10000
#define TSTEPS 20

// ---------------- device scratch (static allocation only) ----------------
__device__ float g_att1[BATCH * RR * ATTD];
__device__ float g_mean[BATCH * ENCD];
__device__ float g_state[BATCH * 1024];            // [h | c]
__device__ float g_hproj[BATCH * 4608];            // [att2 | fbeta_pre | hWhh]
__device__ float g_alpha[BATCH * RR];
__device__ float g_ctx[BATCH * ENCD];
__device__ float g_gadd[BATCH * 2048];
__device__ float g_gpart[4 * BATCH * 2048];        // split-K partials for gates
__device__ float g_H[BATCH * TSTEPS * DECD];       // all h_t, row = b*TSTEPS+t
__device__ float g_E[BATCH * TSTEPS * EMBD];
__device__ float g_embproj[BATCH * TSTEPS * 2048];
__device__ float g_Wcat[4608 * 512];
__device__ float g_bcat[4608];
__device__ float g_bsum[2048];
__device__ float g_Winit[1024 * ENCD];
__device__ float g_binit[1024];

// ---------------- helpers ----------------
__device__ __forceinline__ float f2tf32(float x) {
    float r;
    asm("cvt.rna.tf32.f32 %0, %1;" : "=f"(r) : "f"(x));
    return r;
}

#define MMA_TF32(c, a, b0, b1)                                              \
    asm volatile(                                                           \
        "mma.sync.aligned.m16n8k8.row.col.f32.tf32.tf32.f32 "               \
        "{%0,%1,%2,%3}, {%4,%5,%6,%7}, {%8,%9}, {%0,%1,%2,%3};"             \
        : "+f"(c[0]), "+f"(c[1]), "+f"(c[2]), "+f"(c[3])                    \
        : "r"(a[0]), "r"(a[1]), "r"(a[2]), "r"(a[3]), "r"(b0), "r"(b1))

#define MMA_BF16(c, a, b0, b1)                                              \
    asm volatile(                                                           \
        "mma.sync.aligned.m16n8k16.row.col.f32.bf16.bf16.f32 "              \
        "{%0,%1,%2,%3}, {%4,%5,%6,%7}, {%8,%9}, {%0,%1,%2,%3};"             \
        : "+f"(c[0]), "+f"(c[1]), "+f"(c[2]), "+f"(c[3])                    \
        : "r"(a[0]), "r"(a[1]), "r"(a[2]), "r"(a[3]), "r"(b0), "r"(b1))

__device__ __forceinline__ void cp_async16(uint32_t saddr, const void* gptr, int src_bytes) {
    asm volatile("cp.async.cg.shared.global [%0], [%1], 16, %2;\n"
                 :: "r"(saddr), "l"(gptr), "r"(src_bytes));
}
__device__ __forceinline__ void cp_commit() { asm volatile("cp.async.commit_group;\n"); }

// ================= tf32 single-pass pipelined GEMM (att1 / embproj) =================
#define SROW 36
#define STAGE (128 * SROW + 64 * SROW)

__global__ void __launch_bounds__(256) gemm_pipe(
    const float* __restrict__ A, int lda,
    const float* __restrict__ Bm, int ldb,
    const float* __restrict__ bias,
    float* __restrict__ C, int ldc,
    int N, int K) {
    extern __shared__ float smem[];
    const int tid = threadIdx.x;
    const int m0 = blockIdx.y * 128;
    const int n0 = blockIdx.x * 64;

    const int warp = tid >> 5, lane = tid & 31;
    const int g = lane >> 2, tg = lane & 3;
    const int wm = (warp >> 1) * 32;
    const int wn = (warp & 1) * 32;

    float acc[2][4][4];
#pragma unroll
    for (int mi = 0; mi < 2; mi++)
#pragma unroll
        for (int ni = 0; ni < 4; ni++)
#pragma unroll
            for (int j = 0; j < 4; j++) acc[mi][ni][j] = 0.f;

    const int ntiles = K >> 5;

    auto load_stage = [&](int buf, int kt) {
        float* sA = smem + buf * STAGE;
        float* sB = sA + 128 * SROW;
        const int kb = kt;
#pragma unroll
        for (int i = 0; i < 4; i++) {
            int idx = tid + i * 256;
            int row = idx >> 3;
            int q = (idx & 7) << 2;
            uint32_t d = (uint32_t)__cvta_generic_to_shared(sA + row * SROW + q);
            cp_async16(d, A + (size_t)(m0 + row) * lda + kb + q, 16);
        }
#pragma unroll
        for (int i = 0; i < 2; i++) {
            int idx = tid + i * 256;
            int row = idx >> 3;
            int q = (idx & 7) << 2;
            int nr = n0 + row;
            int ok = (nr < N);
            if (!ok) nr = N - 1;
            uint32_t d = (uint32_t)__cvta_generic_to_shared(sB + row * SROW + q);
            cp_async16(d, Bm + (size_t)nr * ldb + kb + q, ok ? 16 : 0);
        }
        cp_commit();
    };

    load_stage(0, 0);

    for (int kt = 0; kt < ntiles; kt++) {
        if (kt + 1 < ntiles) {
            load_stage((kt + 1) & 1, (kt + 1) << 5);
            asm volatile("cp.async.wait_group 1;\n");
        } else {
            asm volatile("cp.async.wait_group 0;\n");
        }
        __syncthreads();

        const float* sA = smem + (kt & 1) * STAGE;
        const float* sB = sA + 128 * SROW;

#pragma unroll
        for (int ks = 0; ks < 4; ks++) {
            const int k0 = ks * 8;
            unsigned ah[2][4];
#pragma unroll
            for (int mi = 0; mi < 2; mi++) {
                int r = wm + mi * 16;
#pragma unroll
                for (int e = 0; e < 4; e++) {
                    int rr = r + g + ((e & 1) ? 8 : 0);
                    int kk = k0 + tg + ((e & 2) ? 4 : 0);
                    ah[mi][e] = __float_as_uint(f2tf32(sA[rr * SROW + kk]));
                }
            }
#pragma unroll
            for (int ni = 0; ni < 4; ni++) {
                int cb = wn + ni * 8;
                unsigned bh0 = __float_as_uint(f2tf32(sB[(cb + g) * SROW + k0 + tg]));
                unsigned bh1 = __float_as_uint(f2tf32(sB[(cb + g) * SROW + k0 + tg + 4]));
#pragma unroll
                for (int mi = 0; mi < 2; mi++) MMA_TF32(acc[mi][ni], ah[mi], bh0, bh1);
            }
        }
        __syncthreads();
    }

#pragma unroll
    for (int mi = 0; mi < 2; mi++) {
#pragma unroll
        for (int ni = 0; ni < 4; ni++) {
            int r0 = m0 + wm + mi * 16 + g;
            int c0 = n0 + wn + ni * 8 + tg * 2;
#pragma unroll
            for (int half = 0; half < 2; half++) {
                int rr = r0 + half * 8;
#pragma unroll
                for (int j = 0; j < 2; j++) {
                    int cc = c0 + j;
                    if (cc >= N) continue;
                    float v = acc[mi][ni][half * 2 + j];
                    if (bias) v += bias[cc];
                    C[(size_t)rr * ldc + cc] = v;
                }
            }
        }
    }
}

// ================= bf16 hi/lo 3-pass GEMM (precise path) =================
// Tiles BM=128, BN=64, BK=32. 256 threads. LDG->convert->STS packed bf16x2,
// register-double-buffered. smem rows: 16 u32 pairs, stride 17.
#define PROW 17
#define B16_AH 0
#define B16_AL (128 * PROW)
#define B16_BH (2 * 128 * PROW)
#define B16_BL (2 * 128 * PROW + 64 * PROW)
#define B16_STAGE_U32 (2 * 128 * PROW + 2 * 64 * PROW)   // 6528 u32 = 26112 B

__global__ void __launch_bounds__(256) gemm_bf16p(
    const float* __restrict__ A, int lda,
    const float* __restrict__ Bm, int ldb,
    const float* __restrict__ bias,
    const float* __restrict__ Csrc, int ldsrc,
    float* __restrict__ Cbase, int ldc, size_t zstride,
    int N, int K) {
    extern __shared__ uint32_t sm16[];
    const int tid = threadIdx.x;
    const int m0 = blockIdx.y * 128;
    const int n0 = blockIdx.x * 64;
    const int Koff = blockIdx.z * K;
    float* C = Cbase + (size_t)blockIdx.z * zstride;
    const bool final_z = (gridDim.z == 1);

    const int warp = tid >> 5, lane = tid & 31;
    const int g = lane >> 2, tg = lane & 3;
    const int wm = (warp >> 1) * 32;
    const int wn = (warp & 1) * 32;

    float acc[2][4][4];
#pragma unroll
    for (int mi = 0; mi < 2; mi++)
#pragma unroll
        for (int ni = 0; ni < 4; ni++)
#pragma unroll
            for (int j = 0; j < 4; j++) acc[mi][ni][j] = 0.f;

    const int ntiles = K >> 5;
    float4 aR[4];
    float4 bR[2];

    const int a_row = tid >> 3;            // 0..31 base (plus i*32)
    const int a_q = (tid & 7) << 2;        // k offset 0..28 step 4
    const int a_p = (tid & 7) << 1;        // pair offset 0..14 step 2

    auto ldg_tile = [&](int kt) {
        const int kb = Koff + (kt << 5);
#pragma unroll
        for (int i = 0; i < 4; i++) {
            int row = a_row + i * 32;
            aR[i] = *(const float4*)(A + (size_t)(m0 + row) * lda + kb + a_q);
        }
#pragma unroll
        for (int i = 0; i < 2; i++) {
            int row = a_row + i * 32;
            if (n0 + row < N)
                bR[i] = *(const float4*)(Bm + (size_t)(n0 + row) * ldb + kb + a_q);
            else
                bR[i] = make_float4(0.f, 0.f, 0.f, 0.f);
        }
    };

    auto cvt_store = [&](uint32_t* base, int row, const float4& v) {
        __nv_bfloat162 h0 = __float22bfloat162_rn(make_float2(v.x, v.y));
        __nv_bfloat162 h1 = __float22bfloat162_rn(make_float2(v.z, v.w));
        float2 f0 = __bfloat1622float2(h0);
        float2 f1 = __bfloat1622float2(h1);
        __nv_bfloat162 l0 = __float22bfloat162_rn(make_float2(v.x - f0.x, v.y - f0.y));
        __nv_bfloat162 l1 = __float22bfloat162_rn(make_float2(v.z - f1.x, v.w - f1.y));
        base[row * PROW + a_p] = *(const uint32_t*)&h0;
        base[row * PROW + a_p + 1] = *(const uint32_t*)&h1;
        base[(128 * PROW) + row * PROW + a_p] = *(const uint32_t*)&l0;        // lo array follows hi
        base[(128 * PROW) + row * PROW + a_p + 1] = *(const uint32_t*)&l1;
    };
    // NOTE: lo-array offset differs for A (128 rows) and B (64 rows); handle separately.

    auto sts_tile = [&](int buf) {
        uint32_t* s = sm16 + buf * B16_STAGE_U32;
#pragma unroll
        for (int i = 0; i < 4; i++) {
            int row = a_row + i * 32;
            const float4 v = aR[i];
            __nv_bfloat162 h0 = __float22bfloat162_rn(make_float2(v.x, v.y));
            __nv_bfloat162 h1 = __float22bfloat162_rn(make_float2(v.z, v.w));
            float2 f0 = __bfloat1622float2(h0);
            float2 f1 = __bfloat1622float2(h1);
            __nv_bfloat162 l0 = __float22bfloat162_rn(make_float2(v.x - f0.x, v.y - f0.y));
            __nv_bfloat162 l1 = __float22bfloat162_rn(make_float2(v.z - f1.x, v.w - f1.y));
            s[B16_AH + row * PROW + a_p] = *(const uint32_t*)&h0;
            s[B16_AH + row * PROW + a_p + 1] = *(const uint32_t*)&h1;
            s[B16_AL + row * PROW + a_p] = *(const uint32_t*)&l0;
            s[B16_AL + row * PROW + a_p + 1] = *(const uint32_t*)&l1;
        }
#pragma unroll
        for (int i = 0; i < 2; i++) {
            int row = a_row + i * 32;
            const float4 v = bR[i];
            __nv_bfloat162 h0 = __float22bfloat162_rn(make_float2(v.x, v.y));
            __nv_bfloat162 h1 = __float22bfloat162_rn(make_float2(v.z, v.w));
            float2 f0 = __bfloat1622float2(h0);
            float2 f1 = __bfloat1622float2(h1);
            __nv_bfloat162 l0 = __float22bfloat162_rn(make_float2(v.x - f0.x, v.y - f0.y));
            __nv_bfloat162 l1 = __float22bfloat162_rn(make_float2(v.z - f1.x, v.w - f1.y));
            s[B16_BH + row * PROW + a_p] = *(const uint32_t*)&h0;
            s[B16_BH + row * PROW + a_p + 1] = *(const uint32_t*)&h1;
            s[B16_BL + row * PROW + a_p] = *(const uint32_t*)&l0;
            s[B16_BL + row * PROW + a_p + 1] = *(const uint32_t*)&l1;
        }
    };

    ldg_tile(0);
    sts_tile(0);
    __syncthreads();

    for (int kt = 0; kt < ntiles; kt++) {
        if (kt + 1 < ntiles) ldg_tile(kt + 1);

        const uint32_t* s = sm16 + (kt & 1) * B16_STAGE_U32;
#pragma unroll
        for (int ks = 0; ks < 2; ks++) {
            const int k0p = ks * 8;
            unsigned ah[2][4], al[2][4];
#pragma unroll
            for (int mi = 0; mi < 2; mi++) {
                int r = wm + mi * 16;
                ah[mi][0] = s[B16_AH + (r + g) * PROW + k0p + tg];
                ah[mi][1] = s[B16_AH + (r + g + 8) * PROW + k0p + tg];
                ah[mi][2] = s[B16_AH + (r + g) * PROW + k0p + 4 + tg];
                ah[mi][3] = s[B16_AH + (r + g + 8) * PROW + k0p + 4 + tg];
                al[mi][0] = s[B16_AL + (r + g) * PROW + k0p + tg];
                al[mi][1] = s[B16_AL + (r + g + 8) * PROW + k0p + tg];
                al[mi][2] = s[B16_AL + (r + g) * PROW + k0p + 4 + tg];
                al[mi][3] = s[B16_AL + (r + g + 8) * PROW + k0p + 4 + tg];
            }
#pragma unroll
            for (int ni = 0; ni < 4; ni++) {
                int cb = wn + ni * 8;
                unsigned bh0 = s[B16_BH + (cb + g) * PROW + k0p + tg];
                unsigned bh1 = s[B16_BH + (cb + g) * PROW + k0p + 4 + tg];
                unsigned bl0 = s[B16_BL + (cb + g) * PROW + k0p + tg];
                unsigned bl1 = s[B16_BL + (cb + g) * PROW + k0p + 4 + tg];
#pragma unroll
                for (int mi = 0; mi < 2; mi++) {
                    MMA_BF16(acc[mi][ni], ah[mi], bh0, bh1);
                    MMA_BF16(acc[mi][ni], al[mi], bh0, bh1);
                    MMA_BF16(acc[mi][ni], ah[mi], bl0, bl1);
                }
            }
        }

        if (kt + 1 < ntiles) {
            __syncthreads();
            sts_tile((kt + 1) & 1);
            __syncthreads();
        }
    }

    // epilogue
#pragma unroll
    for (int mi = 0; mi < 2; mi++) {
#pragma unroll
        for (int ni = 0; ni < 4; ni++) {
            int r0 = m0 + wm + mi * 16 + g;
            int c0 = n0 + wn + ni * 8 + tg * 2;
#pragma unroll
            for (int half = 0; half < 2; half++) {
                int rr = r0 + half * 8;
#pragma unroll
                for (int j = 0; j < 2; j++) {
                    int cc = c0 + j;
                    if (cc >= N) continue;
                    float v = acc[mi][ni][half * 2 + j];
                    if (final_z) {
                        if (bias) v += bias[cc];
                        if (Csrc) v += Csrc[(size_t)rr * ldsrc + cc];
                    }
                    C[(size_t)rr * ldc + cc] = v;
                }
            }
        }
    }
}

// ---------------- small kernels ----------------
__global__ void bsum_kernel(float* __restrict__ out, const float* __restrict__ a,
                            const float* __restrict__ b) {
    int i = blockIdx.x * blockDim.x + threadIdx.x;
    if (i < 2048) out[i] = a[i] + b[i];
}

__global__ void gather_kernel(const int* __restrict__ cap, const float* __restrict__ table,
                              float* __restrict__ E) {
    int bt = blockIdx.x;
    int b = bt / TSTEPS, tt = bt % TSTEPS;
    int idx = cap[b * (TSTEPS + 1) + tt];
    const float4* src = (const float4*)(table + (size_t)idx * EMBD);
    float4* dst = (float4*)(E + (size_t)bt * EMBD);
    dst[threadIdx.x] = src[threadIdx.x];
}

__global__ void mean_kernel(const float* __restrict__ enc, float* __restrict__ mean) {
    int b = blockIdx.y;
    int e = blockIdx.x * 256 + threadIdx.x;
    const float* ep = enc + (size_t)b * RR * ENCD + e;
    float acc = 0.f;
#pragma unroll 4
    for (int r = 0; r < RR; r++) acc += ep[(size_t)r * ENCD];
    mean[b * ENCD + e] = acc * (1.f / (float)RR);
}

__global__ void __launch_bounds__(512) attention_kernel(
    const float* __restrict__ att1, const float* __restrict__ hproj,
    const float* __restrict__ wfull, const float* __restrict__ bfull,
    float* __restrict__ alpha_out, float* __restrict__ out_alpha, int t) {
    int b = blockIdx.x;
    int tid = threadIdx.x;  // 512
    __shared__ float s_att2[512], s_wf[512], s_sc[RR], s_red[16];
    s_att2[tid] = hproj[b * 4608 + tid];
    s_wf[tid] = wfull[tid];
    __syncthreads();
    int warp = tid >> 5, lane = tid & 31;
    float bf = bfull[0];
    for (int r = warp; r < RR; r += 16) {
        const float* ap = att1 + ((size_t)(b * RR + r)) * 512;
        float s = 0.f;
#pragma unroll 4
        for (int a = lane; a < 512; a += 32) {
            float v = ap[a] + s_att2[a];
            s += fmaxf(v, 0.f) * s_wf[a];
        }
#pragma unroll
        for (int o = 16; o; o >>= 1) s += __shfl_xor_sync(0xffffffffu, s, o);
        if (lane == 0) s_sc[r] = s + bf;
    }
    __syncthreads();
    float m = -1e30f;
    for (int i = tid; i < RR; i += 512) m = fmaxf(m, s_sc[i]);
#pragma unroll
    for (int o = 16; o; o >>= 1) m = fmaxf(m, __shfl_xor_sync(0xffffffffu, m, o));
    if (lane == 0) s_red[warp] = m;
    __syncthreads();
    m = s_red[0];
#pragma unroll
    for (int w = 1; w < 16; w++) m = fmaxf(m, s_red[w]);
    __syncthreads();
    float sum = 0.f;
    for (int i = tid; i < RR; i += 512) {
        float e = expf(s_sc[i] - m);
        s_sc[i] = e;
        sum += e;
    }
#pragma unroll
    for (int o = 16; o; o >>= 1) sum += __shfl_xor_sync(0xffffffffu, sum, o);
    if (lane == 0) s_red[warp] = sum;
    __syncthreads();
    sum = 0.f;
#pragma unroll
    for (int w = 0; w < 16; w++) sum += s_red[w];
    float inv = 1.f / sum;
    for (int i = tid; i < RR; i += 512) {
        float a = s_sc[i] * inv;
        alpha_out[b * RR + i] = a;
        out_alpha[((size_t)b * TSTEPS + t) * RR + i] = a;
    }
}

__global__ void ctx_kernel(const float* __restrict__ enc, const float* __restrict__ alpha,
                           const float* __restrict__ hproj, const float* __restrict__ embproj,
                           float* __restrict__ ctx, float* __restrict__ gadd, int t) {
    int b = blockIdx.y;
    int e = blockIdx.x * 256 + threadIdx.x;
    __shared__ float s_a[RR];
    for (int i = threadIdx.x; i < RR; i += 256) s_a[i] = alpha[b * RR + i];
    __syncthreads();
    const float* ep = enc + (size_t)b * RR * ENCD + e;
    float acc = 0.f;
#pragma unroll 4
    for (int r = 0; r < RR; r++) acc += s_a[r] * ep[(size_t)r * ENCD];
    float gpre = hproj[b * 4608 + 512 + e];
    float gate = 1.f / (1.f + expf(-gpre));
    ctx[b * ENCD + e] = gate * acc;
    gadd[b * 2048 + e] = embproj[((size_t)b * TSTEPS + t) * 2048 + e] + hproj[b * 4608 + 2560 + e];
}

// sums 4 split-K partials + gadd, LSTM pointwise, writes h to state AND g_H[t]
__global__ void lstm_kernel(const float* __restrict__ gpart, const float* __restrict__ gadd,
                            float* __restrict__ state, float* __restrict__ Hout, int t) {
    int b = blockIdx.x, d = threadIdx.x;  // 512 threads
    float gt[4];
#pragma unroll
    for (int q = 0; q < 4; q++) {
        int j = b * 2048 + q * 512 + d;
        float s = gadd[j];
#pragma unroll
        for (int z = 0; z < 4; z++) s += gpart[z * BATCH * 2048 + j];
        gt[q] = s;
    }
    float i_ = 1.f / (1.f + expf(-gt[0]));
    float f_ = 1.f / (1.f + expf(-gt[1]));
    float g_ = tanhf(gt[2]);
    float o_ = 1.f / (1.f + expf(-gt[3]));
    float c = state[b * 1024 + 512 + d];
    float cn = f_ * c + i_ * g_;
    float hn = o_ * tanhf(cn);
    state[b * 1024 + d] = hn;
    state[b * 1024 + 512 + d] = cn;
    Hout[((size_t)b * TSTEPS + t) * DECD + d] = hn;
}

// ---------------- host ----------------
static float* symaddr(const void* sym) {
    void* p = nullptr;
    cudaGetSymbolAddress(&p, sym);
    return (float*)p;
}

static const int TF32_SMEM = 2 * STAGE * 4;            // 55296 bytes
static const int BF16_SMEM = 2 * B16_STAGE_U32 * 4;    // 52224 bytes

static void launch_tf32(const float* A, int lda, const float* B, int ldb,
                        const float* bias, float* C, int ldc, int M, int N, int K) {
    dim3 grid((N + 63) / 64, M / 128, 1);
    gemm_pipe<<<grid, 256, TF32_SMEM>>>(A, lda, B, ldb, bias, C, ldc, N, K);
}

static void launch_bf16p(const float* A, int lda, const float* B, int ldb,
                         const float* bias, const float* Csrc, int ldsrc, float* C, int ldc,
                         size_t zstride, int M, int N, int K, int zsplit) {
    dim3 grid((N + 63) / 64, M / 128, zsplit);
    gemm_bf16p<<<grid, 256, BF16_SMEM>>>(A, lda, B, ldb, bias, Csrc, ldsrc, C, ldc,
                                         zstride, N, K / zsplit);
}

extern "C" void kernel_launch(void* const* d_in, const int* in_sizes, int n_in,
                              void* d_out, int out_size) {
    const float* enc       = (const float*)d_in[0];
    const int*   captions  = (const int*)d_in[1];
    const float* W_enc_att = (const float*)d_in[2];
    const float* b_enc_att = (const float*)d_in[3];
    const float* W_dec_att = (const float*)d_in[4];
    const float* b_dec_att = (const float*)d_in[5];
    const float* W_full    = (const float*)d_in[6];
    const float* b_full    = (const float*)d_in[7];
    const float* emb_table = (const float*)d_in[8];
    const float* W_ih      = (const float*)d_in[9];
    const float* W_hh      = (const float*)d_in[10];
    const float* b_ih      = (const float*)d_in[11];
    const float* b_hh      = (const float*)d_in[12];
    const float* W_init_h  = (const float*)d_in[13];
    const float* b_init_h  = (const float*)d_in[14];
    const float* W_init_c  = (const float*)d_in[15];
    const float* b_init_c  = (const float*)d_in[16];
    const float* W_fbeta   = (const float*)d_in[17];
    const float* b_fbeta   = (const float*)d_in[18];
    const float* W_fc      = (const float*)d_in[19];
    const float* b_fc      = (const float*)d_in[20];

    float* out_pred  = (float*)d_out;
    float* out_alpha = out_pred + (size_t)BATCH * TSTEPS * VOC;

    float* att1   = symaddr(g_att1);
    float* meanb  = symaddr(g_mean);
    float* state  = symaddr(g_state);
    float* hproj  = symaddr(g_hproj);
    float* alpha  = symaddr(g_alpha);
    float* ctx    = symaddr(g_ctx);
    float* gadd   = symaddr(g_gadd);
    float* gpart  = symaddr(g_gpart);
    float* Hbuf   = symaddr(g_H);
    float* E      = symaddr(g_E);
    float* embprj = symaddr(g_embproj);
    float* Wcat   = symaddr(g_Wcat);
    float* bcat   = symaddr(g_bcat);
    float* bsum   = symaddr(g_bsum);
    float* Winit  = symaddr(g_Winit);
    float* binit  = symaddr(g_binit);

    cudaFuncSetAttribute(gemm_pipe, cudaFuncAttributeMaxDynamicSharedMemorySize, TF32_SMEM);
    cudaFuncSetAttribute(gemm_bf16p, cudaFuncAttributeMaxDynamicSharedMemorySize, BF16_SMEM);

    // ---- prologue: weight concats ----
    cudaMemcpyAsync(Wcat, W_dec_att, (size_t)512 * 512 * 4, cudaMemcpyDeviceToDevice, 0);
    cudaMemcpyAsync(Wcat + 512 * 512, W_fbeta, (size_t)2048 * 512 * 4, cudaMemcpyDeviceToDevice, 0);
    cudaMemcpyAsync(Wcat + 2560 * 512, W_hh, (size_t)2048 * 512 * 4, cudaMemcpyDeviceToDevice, 0);
    cudaMemcpyAsync(bcat, b_dec_att, 512 * 4, cudaMemcpyDeviceToDevice, 0);
    cudaMemcpyAsync(bcat + 512, b_fbeta, 2048 * 4, cudaMemcpyDeviceToDevice, 0);
    cudaMemsetAsync(bcat + 2560, 0, 2048 * 4, 0);
    cudaMemcpyAsync(Winit, W_init_h, (size_t)512 * 2048 * 4, cudaMemcpyDeviceToDevice, 0);
    cudaMemcpyAsync(Winit + (size_t)512 * 2048, W_init_c, (size_t)512 * 2048 * 4,
                    cudaMemcpyDeviceToDevice, 0);
    cudaMemcpyAsync(binit, b_init_h, 512 * 4, cudaMemcpyDeviceToDevice, 0);
    cudaMemcpyAsync(binit + 512, b_init_c, 512 * 4, cudaMemcpyDeviceToDevice, 0);

    bsum_kernel<<<8, 256>>>(bsum, b_ih, b_hh);
    mean_kernel<<<dim3(8, BATCH), 256>>>(enc, meanb);
    // state = mean @ [W_init_h; W_init_c]^T + [b_init_h; b_init_c]   (precise bf16 3-pass)
    launch_bf16p(meanb, ENCD, Winit, ENCD, binit, nullptr, 0, state, 1024, 0,
                 BATCH, 1024, ENCD, 1);
    gather_kernel<<<BATCH * TSTEPS, 128>>>(captions, emb_table, E);
    // embproj (all t): E @ W_ih[:, :512]^T + (b_ih + b_hh)   (tf32 1-pass)
    launch_tf32(E, EMBD, W_ih, EMBD + ENCD, bsum, embprj, 2048, BATCH * TSTEPS, 2048, EMBD);
    // att1 = enc @ W_enc_att^T + b_enc_att   (tf32 1-pass)
    launch_tf32(enc, ENCD, W_enc_att, ENCD, b_enc_att, att1, ATTD, BATCH * RR, ATTD, ENCD);

    // ---- recurrence (fc hoisted) ----
    for (int t = 0; t < TSTEPS; t++) {
        // hproj = h @ [W_dec_att; W_fbeta; W_hh]^T + [b_dec_att; b_fbeta; 0]
        launch_bf16p(state, 1024, Wcat, 512, bcat, nullptr, 0, hproj, 4608, 0,
                     BATCH, 4608, DECD, 1);
        attention_kernel<<<BATCH, 512>>>(att1, hproj, W_full, b_full, alpha, out_alpha, t);
        ctx_kernel<<<dim3(8, BATCH), 256>>>(enc, alpha, hproj, embprj, ctx, gadd, t);
        // gates partials = ctx @ W_ih[:, 512:]^T   (split-K = 4)
        launch_bf16p(ctx, ENCD, W_ih + 512, EMBD + ENCD, nullptr, nullptr, 0, gpart, 2048,
                     (size_t)BATCH * 2048, BATCH, 2048, ENCD, 4);
        lstm_kernel<<<BATCH, 512>>>(gpart, gadd, state, Hbuf, t);
    }

    // ---- batched fc: preds[b,t,:] = h_t @ W_fc^T + b_fc ----
    launch_bf16p(Hbuf, DECD, W_fc, DECD, b_fc, nullptr, 0, out_pred, VOC, 0,
                 BATCH * TSTEPS, VOC, DECD, 1);
}

// round 8
// speedup vs baseline: 3.0536x; 1.1062x over previous
#include <cuda_runtime.h>
#include <cuda_bf16.h>
#include <cuda_fp16.h>
#include <cstdint>
#include <cstddef>

#define BATCH 128
#define RR    196
#define ENCD  2048
#define ATTD  512
#define DECD  512
#define EMBD  512
#define VOC   10000
#define TSTEPS 20

// ---------------- device scratch (static allocation only) ----------------
__device__ float g_att1[BATCH * RR * ATTD];
__device__ __half g_ench[(size_t)BATCH * RR * ENCD];   // 102.8 MB fp16 mirror of enc
__device__ float g_mean[BATCH * ENCD];
__device__ float g_state[BATCH * 1024];            // [h | c]
__device__ float g_hproj[BATCH * 4608];            // [att2 | fbeta_pre | hWhh]
__device__ float g_alpha[BATCH * RR];
__device__ float g_ctx[BATCH * ENCD];
__device__ float g_gadd[BATCH * 2048];
__device__ float g_gpart[4 * BATCH * 2048];        // split-K partials for gates
__device__ float g_H[BATCH * TSTEPS * DECD];       // all h_t, row = b*TSTEPS+t
__device__ float g_E[BATCH * TSTEPS * EMBD];
__device__ float g_embproj[BATCH * TSTEPS * 2048];
__device__ float g_Wcat[4608 * 512];
__device__ float g_bcat[4608];
__device__ float g_bsum[2048];
__device__ float g_Winit[1024 * ENCD];
__device__ float g_binit[1024];

// ---------------- helpers ----------------
__device__ __forceinline__ float f2tf32(float x) {
    float r;
    asm("cvt.rna.tf32.f32 %0, %1;" : "=f"(r) : "f"(x));
    return r;
}

#define MMA_TF32(c, a, b0, b1)                                              \
    asm volatile(                                                           \
        "mma.sync.aligned.m16n8k8.row.col.f32.tf32.tf32.f32 "               \
        "{%0,%1,%2,%3}, {%4,%5,%6,%7}, {%8,%9}, {%0,%1,%2,%3};"             \
        : "+f"(c[0]), "+f"(c[1]), "+f"(c[2]), "+f"(c[3])                    \
        : "r"(a[0]), "r"(a[1]), "r"(a[2]), "r"(a[3]), "r"(b0), "r"(b1))

#define MMA_BF16(c, a, b0, b1)                                              \
    asm volatile(                                                           \
        "mma.sync.aligned.m16n8k16.row.col.f32.bf16.bf16.f32 "              \
        "{%0,%1,%2,%3}, {%4,%5,%6,%7}, {%8,%9}, {%0,%1,%2,%3};"             \
        : "+f"(c[0]), "+f"(c[1]), "+f"(c[2]), "+f"(c[3])                    \
        : "r"(a[0]), "r"(a[1]), "r"(a[2]), "r"(a[3]), "r"(b0), "r"(b1))

__device__ __forceinline__ void cp_async16(uint32_t saddr, const void* gptr, int src_bytes) {
    asm volatile("cp.async.cg.shared.global [%0], [%1], 16, %2;\n"
                 :: "r"(saddr), "l"(gptr), "r"(src_bytes));
}
__device__ __forceinline__ void cp_commit() { asm volatile("cp.async.commit_group;\n"); }

// ================= tf32 single-pass pipelined GEMM (att1 / embproj) =================
#define SROW 36
#define STAGE (128 * SROW + 64 * SROW)

__global__ void __launch_bounds__(256) gemm_pipe(
    const float* __restrict__ A, int lda,
    const float* __restrict__ Bm, int ldb,
    const float* __restrict__ bias,
    float* __restrict__ C, int ldc,
    int N, int K) {
    extern __shared__ float smem[];
    const int tid = threadIdx.x;
    const int m0 = blockIdx.y * 128;
    const int n0 = blockIdx.x * 64;

    const int warp = tid >> 5, lane = tid & 31;
    const int g = lane >> 2, tg = lane & 3;
    const int wm = (warp >> 1) * 32;
    const int wn = (warp & 1) * 32;

    float acc[2][4][4];
#pragma unroll
    for (int mi = 0; mi < 2; mi++)
#pragma unroll
        for (int ni = 0; ni < 4; ni++)
#pragma unroll
            for (int j = 0; j < 4; j++) acc[mi][ni][j] = 0.f;

    const int ntiles = K >> 5;

    auto load_stage = [&](int buf, int kt) {
        float* sA = smem + buf * STAGE;
        float* sB = sA + 128 * SROW;
        const int kb = kt;
#pragma unroll
        for (int i = 0; i < 4; i++) {
            int idx = tid + i * 256;
            int row = idx >> 3;
            int q = (idx & 7) << 2;
            uint32_t d = (uint32_t)__cvta_generic_to_shared(sA + row * SROW + q);
            cp_async16(d, A + (size_t)(m0 + row) * lda + kb + q, 16);
        }
#pragma unroll
        for (int i = 0; i < 2; i++) {
            int idx = tid + i * 256;
            int row = idx >> 3;
            int q = (idx & 7) << 2;
            int nr = n0 + row;
            int ok = (nr < N);
            if (!ok) nr = N - 1;
            uint32_t d = (uint32_t)__cvta_generic_to_shared(sB + row * SROW + q);
            cp_async16(d, Bm + (size_t)nr * ldb + kb + q, ok ? 16 : 0);
        }
        cp_commit();
    };

    load_stage(0, 0);

    for (int kt = 0; kt < ntiles; kt++) {
        if (kt + 1 < ntiles) {
            load_stage((kt + 1) & 1, (kt + 1) << 5);
            asm volatile("cp.async.wait_group 1;\n");
        } else {
            asm volatile("cp.async.wait_group 0;\n");
        }
        __syncthreads();

        const float* sA = smem + (kt & 1) * STAGE;
        const float* sB = sA + 128 * SROW;

#pragma unroll
        for (int ks = 0; ks < 4; ks++) {
            const int k0 = ks * 8;
            unsigned ah[2][4];
#pragma unroll
            for (int mi = 0; mi < 2; mi++) {
                int r = wm + mi * 16;
#pragma unroll
                for (int e = 0; e < 4; e++) {
                    int rr = r + g + ((e & 1) ? 8 : 0);
                    int kk = k0 + tg + ((e & 2) ? 4 : 0);
                    ah[mi][e] = __float_as_uint(f2tf32(sA[rr * SROW + kk]));
                }
            }
#pragma unroll
            for (int ni = 0; ni < 4; ni++) {
                int cb = wn + ni * 8;
                unsigned bh0 = __float_as_uint(f2tf32(sB[(cb + g) * SROW + k0 + tg]));
                unsigned bh1 = __float_as_uint(f2tf32(sB[(cb + g) * SROW + k0 + tg + 4]));
#pragma unroll
                for (int mi = 0; mi < 2; mi++) MMA_TF32(acc[mi][ni], ah[mi], bh0, bh1);
            }
        }
        __syncthreads();
    }

#pragma unroll
    for (int mi = 0; mi < 2; mi++) {
#pragma unroll
        for (int ni = 0; ni < 4; ni++) {
            int r0 = m0 + wm + mi * 16 + g;
            int c0 = n0 + wn + ni * 8 + tg * 2;
#pragma unroll
            for (int half = 0; half < 2; half++) {
                int rr = r0 + half * 8;
#pragma unroll
                for (int j = 0; j < 2; j++) {
                    int cc = c0 + j;
                    if (cc >= N) continue;
                    float v = acc[mi][ni][half * 2 + j];
                    if (bias) v += bias[cc];
                    C[(size_t)rr * ldc + cc] = v;
                }
            }
        }
    }
}

// ================= bf16 hi/lo 3-pass GEMM (precise path) =================
#define PROW 17
#define B16_AH 0
#define B16_AL (128 * PROW)
#define B16_BH (2 * 128 * PROW)
#define B16_BL (2 * 128 * PROW + 64 * PROW)
#define B16_STAGE_U32 (2 * 128 * PROW + 2 * 64 * PROW)   // 6528 u32

__global__ void __launch_bounds__(256) gemm_bf16p(
    const float* __restrict__ A, int lda,
    const float* __restrict__ Bm, int ldb,
    const float* __restrict__ bias,
    const float* __restrict__ Csrc, int ldsrc,
    float* __restrict__ Cbase, int ldc, size_t zstride,
    int N, int K) {
    extern __shared__ uint32_t sm16[];
    const int tid = threadIdx.x;
    const int m0 = blockIdx.y * 128;
    const int n0 = blockIdx.x * 64;
    const int Koff = blockIdx.z * K;
    float* C = Cbase + (size_t)blockIdx.z * zstride;
    const bool final_z = (gridDim.z == 1);

    const int warp = tid >> 5, lane = tid & 31;
    const int g = lane >> 2, tg = lane & 3;
    const int wm = (warp >> 1) * 32;
    const int wn = (warp & 1) * 32;

    float acc[2][4][4];
#pragma unroll
    for (int mi = 0; mi < 2; mi++)
#pragma unroll
        for (int ni = 0; ni < 4; ni++)
#pragma unroll
            for (int j = 0; j < 4; j++) acc[mi][ni][j] = 0.f;

    const int ntiles = K >> 5;
    float4 aR[4];
    float4 bR[2];

    const int a_row = tid >> 3;
    const int a_q = (tid & 7) << 2;
    const int a_p = (tid & 7) << 1;

    auto ldg_tile = [&](int kt) {
        const int kb = Koff + (kt << 5);
#pragma unroll
        for (int i = 0; i < 4; i++) {
            int row = a_row + i * 32;
            aR[i] = *(const float4*)(A + (size_t)(m0 + row) * lda + kb + a_q);
        }
#pragma unroll
        for (int i = 0; i < 2; i++) {
            int row = a_row + i * 32;
            if (n0 + row < N)
                bR[i] = *(const float4*)(Bm + (size_t)(n0 + row) * ldb + kb + a_q);
            else
                bR[i] = make_float4(0.f, 0.f, 0.f, 0.f);
        }
    };

    auto sts_tile = [&](int buf) {
        uint32_t* s = sm16 + buf * B16_STAGE_U32;
#pragma unroll
        for (int i = 0; i < 4; i++) {
            int row = a_row + i * 32;
            const float4 v = aR[i];
            __nv_bfloat162 h0 = __float22bfloat162_rn(make_float2(v.x, v.y));
            __nv_bfloat162 h1 = __float22bfloat162_rn(make_float2(v.z, v.w));
            float2 f0 = __bfloat1622float2(h0);
            float2 f1 = __bfloat1622float2(h1);
            __nv_bfloat162 l0 = __float22bfloat162_rn(make_float2(v.x - f0.x, v.y - f0.y));
            __nv_bfloat162 l1 = __float22bfloat162_rn(make_float2(v.z - f1.x, v.w - f1.y));
            s[B16_AH + row * PROW + a_p] = *(const uint32_t*)&h0;
            s[B16_AH + row * PROW + a_p + 1] = *(const uint32_t*)&h1;
            s[B16_AL + row * PROW + a_p] = *(const uint32_t*)&l0;
            s[B16_AL + row * PROW + a_p + 1] = *(const uint32_t*)&l1;
        }
#pragma unroll
        for (int i = 0; i < 2; i++) {
            int row = a_row + i * 32;
            const float4 v = bR[i];
            __nv_bfloat162 h0 = __float22bfloat162_rn(make_float2(v.x, v.y));
            __nv_bfloat162 h1 = __float22bfloat162_rn(make_float2(v.z, v.w));
            float2 f0 = __bfloat1622float2(h0);
            float2 f1 = __bfloat1622float2(h1);
            __nv_bfloat162 l0 = __float22bfloat162_rn(make_float2(v.x - f0.x, v.y - f0.y));
            __nv_bfloat162 l1 = __float22bfloat162_rn(make_float2(v.z - f1.x, v.w - f1.y));
            s[B16_BH + row * PROW + a_p] = *(const uint32_t*)&h0;
            s[B16_BH + row * PROW + a_p + 1] = *(const uint32_t*)&h1;
            s[B16_BL + row * PROW + a_p] = *(const uint32_t*)&l0;
            s[B16_BL + row * PROW + a_p + 1] = *(const uint32_t*)&l1;
        }
    };

    ldg_tile(0);
    sts_tile(0);
    __syncthreads();

    for (int kt = 0; kt < ntiles; kt++) {
        if (kt + 1 < ntiles) ldg_tile(kt + 1);

        const uint32_t* s = sm16 + (kt & 1) * B16_STAGE_U32;
#pragma unroll
        for (int ks = 0; ks < 2; ks++) {
            const int k0p = ks * 8;
            unsigned ah[2][4], al[2][4];
#pragma unroll
            for (int mi = 0; mi < 2; mi++) {
                int r = wm + mi * 16;
                ah[mi][0] = s[B16_AH + (r + g) * PROW + k0p + tg];
                ah[mi][1] = s[B16_AH + (r + g + 8) * PROW + k0p + tg];
                ah[mi][2] = s[B16_AH + (r + g) * PROW + k0p + 4 + tg];
                ah[mi][3] = s[B16_AH + (r + g + 8) * PROW + k0p + 4 + tg];
                al[mi][0] = s[B16_AL + (r + g) * PROW + k0p + tg];
                al[mi][1] = s[B16_AL + (r + g + 8) * PROW + k0p + tg];
                al[mi][2] = s[B16_AL + (r + g) * PROW + k0p + 4 + tg];
                al[mi][3] = s[B16_AL + (r + g + 8) * PROW + k0p + 4 + tg];
            }
#pragma unroll
            for (int ni = 0; ni < 4; ni++) {
                int cb = wn + ni * 8;
                unsigned bh0 = s[B16_BH + (cb + g) * PROW + k0p + tg];
                unsigned bh1 = s[B16_BH + (cb + g) * PROW + k0p + 4 + tg];
                unsigned bl0 = s[B16_BL + (cb + g) * PROW + k0p + tg];
                unsigned bl1 = s[B16_BL + (cb + g) * PROW + k0p + 4 + tg];
#pragma unroll
                for (int mi = 0; mi < 2; mi++) {
                    MMA_BF16(acc[mi][ni], ah[mi], bh0, bh1);
                    MMA_BF16(acc[mi][ni], al[mi], bh0, bh1);
                    MMA_BF16(acc[mi][ni], ah[mi], bl0, bl1);
                }
            }
        }

        if (kt + 1 < ntiles) {
            __syncthreads();
            sts_tile((kt + 1) & 1);
            __syncthreads();
        }
    }

#pragma unroll
    for (int mi = 0; mi < 2; mi++) {
#pragma unroll
        for (int ni = 0; ni < 4; ni++) {
            int r0 = m0 + wm + mi * 16 + g;
            int c0 = n0 + wn + ni * 8 + tg * 2;
#pragma unroll
            for (int half = 0; half < 2; half++) {
                int rr = r0 + half * 8;
#pragma unroll
                for (int j = 0; j < 2; j++) {
                    int cc = c0 + j;
                    if (cc >= N) continue;
                    float v = acc[mi][ni][half * 2 + j];
                    if (final_z) {
                        if (bias) v += bias[cc];
                        if (Csrc) v += Csrc[(size_t)rr * ldsrc + cc];
                    }
                    C[(size_t)rr * ldc + cc] = v;
                }
            }
        }
    }
}

// ---------------- small kernels ----------------
__global__ void bsum_kernel(float* __restrict__ out, const float* __restrict__ a,
                            const float* __restrict__ b) {
    int i = blockIdx.x * blockDim.x + threadIdx.x;
    if (i < 2048) out[i] = a[i] + b[i];
}

__global__ void gather_kernel(const int* __restrict__ cap, const float* __restrict__ table,
                              float* __restrict__ E) {
    int bt = blockIdx.x;
    int b = bt / TSTEPS, tt = bt % TSTEPS;
    int idx = cap[b * (TSTEPS + 1) + tt];
    const float4* src = (const float4*)(table + (size_t)idx * EMBD);
    float4* dst = (float4*)(E + (size_t)bt * EMBD);
    dst[threadIdx.x] = src[threadIdx.x];
}

// single pass over enc: compute mean AND write fp16 mirror
__global__ void prep_enc_kernel(const float* __restrict__ enc, __half* __restrict__ ench,
                                float* __restrict__ mean) {
    int b = blockIdx.y;
    int e = blockIdx.x * 256 + threadIdx.x;   // 8x256 = 2048
    const float* ep = enc + (size_t)b * RR * ENCD + e;
    __half* op = ench + (size_t)b * RR * ENCD + e;
    float acc = 0.f;
#pragma unroll 4
    for (int r = 0; r < RR; r++) {
        float v = ep[(size_t)r * ENCD];
        acc += v;
        op[(size_t)r * ENCD] = __float2half_rn(v);
    }
    mean[b * ENCD + e] = acc * (1.f / (float)RR);
}

__global__ void __launch_bounds__(1024) attention_kernel(
    const float* __restrict__ att1, const float* __restrict__ hproj,
    const float* __restrict__ wfull, const float* __restrict__ bfull,
    float* __restrict__ alpha_out, float* __restrict__ out_alpha, int t) {
    int b = blockIdx.x;
    int tid = threadIdx.x;  // 1024
    __shared__ float s_att2[512], s_wf[512], s_sc[RR], s_red[32];
    if (tid < 512) {
        s_att2[tid] = hproj[b * 4608 + tid];
        s_wf[tid] = wfull[tid];
    }
    __syncthreads();
    int warp = tid >> 5, lane = tid & 31;
    float bf = bfull[0];
    for (int r = warp; r < RR; r += 32) {
        const float* ap = att1 + ((size_t)(b * RR + r)) * 512;
        float s = 0.f;
#pragma unroll 4
        for (int a = lane; a < 512; a += 32) {
            float v = ap[a] + s_att2[a];
            s += fmaxf(v, 0.f) * s_wf[a];
        }
#pragma unroll
        for (int o = 16; o; o >>= 1) s += __shfl_xor_sync(0xffffffffu, s, o);
        if (lane == 0) s_sc[r] = s + bf;
    }
    __syncthreads();
    float m = -1e30f;
    for (int i = tid; i < RR; i += 1024) m = fmaxf(m, s_sc[i]);
#pragma unroll
    for (int o = 16; o; o >>= 1) m = fmaxf(m, __shfl_xor_sync(0xffffffffu, m, o));
    if (lane == 0) s_red[warp] = m;
    __syncthreads();
    m = s_red[0];
#pragma unroll
    for (int w = 1; w < 32; w++) m = fmaxf(m, s_red[w]);
    __syncthreads();
    float sum = 0.f;
    for (int i = tid; i < RR; i += 1024) {
        float e = expf(s_sc[i] - m);
        s_sc[i] = e;
        sum += e;
    }
#pragma unroll
    for (int o = 16; o; o >>= 1) sum += __shfl_xor_sync(0xffffffffu, sum, o);
    if (lane == 0) s_red[warp] = sum;
    __syncthreads();
    sum = 0.f;
#pragma unroll
    for (int w = 0; w < 32; w++) sum += s_red[w];
    float inv = 1.f / sum;
    for (int i = tid; i < RR; i += 1024) {
        float a = s_sc[i] * inv;
        alpha_out[b * RR + i] = a;
        out_alpha[((size_t)b * TSTEPS + t) * RR + i] = a;
    }
}

// fp16 enc context gather; thread handles an e-pair
__global__ void ctx_kernel(const __half2* __restrict__ ench,
                           const float* __restrict__ alpha,
                           const float* __restrict__ hproj, const float* __restrict__ embproj,
                           float* __restrict__ ctx, float* __restrict__ gadd, int t) {
    int b = blockIdx.y;
    int e2 = blockIdx.x * 256 + threadIdx.x;   // 0..1023 (pair index)
    __shared__ float s_a[RR];
    for (int i = threadIdx.x; i < RR; i += 256) s_a[i] = alpha[b * RR + i];
    __syncthreads();
    const __half2* ep = ench + (size_t)b * RR * (ENCD / 2) + e2;
    float ax = 0.f, ay = 0.f;
#pragma unroll 4
    for (int r = 0; r < RR; r++) {
        float2 f = __half22float2(ep[(size_t)r * (ENCD / 2)]);
        float a = s_a[r];
        ax += a * f.x;
        ay += a * f.y;
    }
    int e = e2 * 2;
    float g0 = hproj[b * 4608 + 512 + e];
    float g1 = hproj[b * 4608 + 512 + e + 1];
    ctx[b * ENCD + e]     = ax / (1.f + expf(-g0));
    ctx[b * ENCD + e + 1] = ay / (1.f + expf(-g1));
    const float* ebp = embproj + ((size_t)b * TSTEPS + t) * 2048;
    gadd[b * 2048 + e]     = ebp[e] + hproj[b * 4608 + 2560 + e];
    gadd[b * 2048 + e + 1] = ebp[e + 1] + hproj[b * 4608 + 2560 + e + 1];
}

// sums 4 split-K partials + gadd, LSTM pointwise, writes h to state AND g_H[t]
__global__ void lstm_kernel(const float* __restrict__ gpart, const float* __restrict__ gadd,
                            float* __restrict__ state, float* __restrict__ Hout, int t) {
    int b = blockIdx.x, d = threadIdx.x;  // 512 threads
    float gt[4];
#pragma unroll
    for (int q = 0; q < 4; q++) {
        int j = b * 2048 + q * 512 + d;
        float s = gadd[j];
#pragma unroll
        for (int z = 0; z < 4; z++) s += gpart[z * BATCH * 2048 + j];
        gt[q] = s;
    }
    float i_ = 1.f / (1.f + expf(-gt[0]));
    float f_ = 1.f / (1.f + expf(-gt[1]));
    float g_ = tanhf(gt[2]);
    float o_ = 1.f / (1.f + expf(-gt[3]));
    float c = state[b * 1024 + 512 + d];
    float cn = f_ * c + i_ * g_;
    float hn = o_ * tanhf(cn);
    state[b * 1024 + d] = hn;
    state[b * 1024 + 512 + d] = cn;
    Hout[((size_t)b * TSTEPS + t) * DECD + d] = hn;
}

// ---------------- host ----------------
static float* symaddr(const void* sym) {
    void* p = nullptr;
    cudaGetSymbolAddress(&p, sym);
    return (float*)p;
}

static const int TF32_SMEM = 2 * STAGE * 4;
static const int BF16_SMEM = 2 * B16_STAGE_U32 * 4;

static void launch_tf32(const float* A, int lda, const float* B, int ldb,
                        const float* bias, float* C, int ldc, int M, int N, int K) {
    dim3 grid((N + 63) / 64, M / 128, 1);
    gemm_pipe<<<grid, 256, TF32_SMEM>>>(A, lda, B, ldb, bias, C, ldc, N, K);
}

static void launch_bf16p(const float* A, int lda, const float* B, int ldb,
                         const float* bias, const float* Csrc, int ldsrc, float* C, int ldc,
                         size_t zstride, int M, int N, int K, int zsplit) {
    dim3 grid((N + 63) / 64, M / 128, zsplit);
    gemm_bf16p<<<grid, 256, BF16_SMEM>>>(A, lda, B, ldb, bias, Csrc, ldsrc, C, ldc,
                                         zstride, N, K / zsplit);
}

extern "C" void kernel_launch(void* const* d_in, const int* in_sizes, int n_in,
                              void* d_out, int out_size) {
    const float* enc       = (const float*)d_in[0];
    const int*   captions  = (const int*)d_in[1];
    const float* W_enc_att = (const float*)d_in[2];
    const float* b_enc_att = (const float*)d_in[3];
    const float* W_dec_att = (const float*)d_in[4];
    const float* b_dec_att = (const float*)d_in[5];
    const float* W_full    = (const float*)d_in[6];
    const float* b_full    = (const float*)d_in[7];
    const float* emb_table = (const float*)d_in[8];
    const float* W_ih      = (const float*)d_in[9];
    const float* W_hh      = (const float*)d_in[10];
    const float* b_ih      = (const float*)d_in[11];
    const float* b_hh      = (const float*)d_in[12];
    const float* W_init_h  = (const float*)d_in[13];
    const float* b_init_h  = (const float*)d_in[14];
    const float* W_init_c  = (const float*)d_in[15];
    const float* b_init_c  = (const float*)d_in[16];
    const float* W_fbeta   = (const float*)d_in[17];
    const float* b_fbeta   = (const float*)d_in[18];
    const float* W_fc      = (const float*)d_in[19];
    const float* b_fc      = (const float*)d_in[20];

    float* out_pred  = (float*)d_out;
    float* out_alpha = out_pred + (size_t)BATCH * TSTEPS * VOC;

    float* att1   = symaddr(g_att1);
    __half* ench  = (__half*)symaddr(g_ench);
    float* meanb  = symaddr(g_mean);
    float* state  = symaddr(g_state);
    float* hproj  = symaddr(g_hproj);
    float* alpha  = symaddr(g_alpha);
    float* ctx    = symaddr(g_ctx);
    float* gadd   = symaddr(g_gadd);
    float* gpart  = symaddr(g_gpart);
    float* Hbuf   = symaddr(g_H);
    float* E      = symaddr(g_E);
    float* embprj = symaddr(g_embproj);
    float* Wcat   = symaddr(g_Wcat);
    float* bcat   = symaddr(g_bcat);
    float* bsum   = symaddr(g_bsum);
    float* Winit  = symaddr(g_Winit);
    float* binit  = symaddr(g_binit);

    cudaFuncSetAttribute(gemm_pipe, cudaFuncAttributeMaxDynamicSharedMemorySize, TF32_SMEM);
    cudaFuncSetAttribute(gemm_bf16p, cudaFuncAttributeMaxDynamicSharedMemorySize, BF16_SMEM);

    // ---- prologue: weight concats ----
    cudaMemcpyAsync(Wcat, W_dec_att, (size_t)512 * 512 * 4, cudaMemcpyDeviceToDevice, 0);
    cudaMemcpyAsync(Wcat + 512 * 512, W_fbeta, (size_t)2048 * 512 * 4, cudaMemcpyDeviceToDevice, 0);
    cudaMemcpyAsync(Wcat + 2560 * 512, W_hh, (size_t)2048 * 512 * 4, cudaMemcpyDeviceToDevice, 0);
    cudaMemcpyAsync(bcat, b_dec_att, 512 * 4, cudaMemcpyDeviceToDevice, 0);
    cudaMemcpyAsync(bcat + 512, b_fbeta, 2048 * 4, cudaMemcpyDeviceToDevice, 0);
    cudaMemsetAsync(bcat + 2560, 0, 2048 * 4, 0);
    cudaMemcpyAsync(Winit, W_init_h, (size_t)512 * 2048 * 4, cudaMemcpyDeviceToDevice, 0);
    cudaMemcpyAsync(Winit + (size_t)512 * 2048, W_init_c, (size_t)512 * 2048 * 4,
                    cudaMemcpyDeviceToDevice, 0);
    cudaMemcpyAsync(binit, b_init_h, 512 * 4, cudaMemcpyDeviceToDevice, 0);
    cudaMemcpyAsync(binit + 512, b_init_c, 512 * 4, cudaMemcpyDeviceToDevice, 0);

    bsum_kernel<<<8, 256>>>(bsum, b_ih, b_hh);
    // one pass over enc: mean + fp16 mirror
    prep_enc_kernel<<<dim3(8, BATCH), 256>>>(enc, ench, meanb);
    // state = mean @ [W_init_h; W_init_c]^T + [b_init_h; b_init_c]
    launch_bf16p(meanb, ENCD, Winit, ENCD, binit, nullptr, 0, state, 1024, 0,
                 BATCH, 1024, ENCD, 1);
    gather_kernel<<<BATCH * TSTEPS, 128>>>(captions, emb_table, E);
    // embproj (all t): E @ W_ih[:, :512]^T + (b_ih + b_hh)
    launch_tf32(E, EMBD, W_ih, EMBD + ENCD, bsum, embprj, 2048, BATCH * TSTEPS, 2048, EMBD);
    // att1 = enc @ W_enc_att^T + b_enc_att
    launch_tf32(enc, ENCD, W_enc_att, ENCD, b_enc_att, att1, ATTD, BATCH * RR, ATTD, ENCD);

    // ---- recurrence (fc hoisted) ----
    for (int t = 0; t < TSTEPS; t++) {
        // hproj = h @ [W_dec_att; W_fbeta; W_hh]^T + [b_dec_att; b_fbeta; 0]
        launch_bf16p(state, 1024, Wcat, 512, bcat, nullptr, 0, hproj, 4608, 0,
                     BATCH, 4608, DECD, 1);
        attention_kernel<<<BATCH, 1024>>>(att1, hproj, W_full, b_full, alpha, out_alpha, t);
        ctx_kernel<<<dim3(4, BATCH), 256>>>((const __half2*)ench, alpha, hproj, embprj,
                                            ctx, gadd, t);
        // gates partials = ctx @ W_ih[:, 512:]^T   (split-K = 4)
        launch_bf16p(ctx, ENCD, W_ih + 512, EMBD + ENCD, nullptr, nullptr, 0, gpart, 2048,
                     (size_t)BATCH * 2048, BATCH, 2048, ENCD, 4);
        lstm_kernel<<<BATCH, 512>>>(gpart, gadd, state, Hbuf, t);
    }

    // ---- batched fc: preds[b,t,:] = h_t @ W_fc^T + b_fc ----
    launch_bf16p(Hbuf, DECD, W_fc, DECD, b_fc, nullptr, 0, out_pred, VOC, 0,
                 BATCH * TSTEPS, VOC, DECD, 1);
}

// round 9
// speedup vs baseline: 3.0957x; 1.0138x over previous
#include <cuda_runtime.h>
#include <cuda_bf16.h>
#include <cuda_fp16.h>
#include <cstdint>
#include <cstddef>

#define BATCH 128
#define RR    196
#define ENCD  2048
#define ATTD  512
#define DECD  512
#define EMBD  512
#define VOC   10000
#define TSTEPS 20

// ---------------- device scratch (static allocation only) ----------------
__device__ __half g_att1h[(size_t)BATCH * RR * ATTD];   // fp16 att1 (25.7 MB)
__device__ __half g_ench[(size_t)BATCH * RR * ENCD];    // fp16 mirror of enc (102.8 MB)
__device__ float g_mean[BATCH * ENCD];
__device__ float g_state[BATCH * 1024];            // [h | c]
__device__ float g_hproj[BATCH * 4608];            // [att2 | fbeta_pre | hWhh]
__device__ float g_ctx[BATCH * ENCD];
__device__ float g_gadd[BATCH * 2048];
__device__ float g_gpart[4 * BATCH * 2048];        // split-K partials for gates
__device__ float g_H[BATCH * TSTEPS * DECD];       // all h_t, row = b*TSTEPS+t
__device__ float g_E[BATCH * TSTEPS * EMBD];
__device__ float g_embproj[BATCH * TSTEPS * 2048];
__device__ float g_Wcat[4608 * 512];
__device__ float g_bcat[4608];
__device__ float g_bsum[2048];
__device__ float g_Winit[1024 * ENCD];
__device__ float g_binit[1024];

// ---------------- helpers ----------------
#define MMA_F16(c, a, b0, b1)                                               \
    asm volatile(                                                           \
        "mma.sync.aligned.m16n8k16.row.col.f32.f16.f16.f32 "                \
        "{%0,%1,%2,%3}, {%4,%5,%6,%7}, {%8,%9}, {%0,%1,%2,%3};"             \
        : "+f"(c[0]), "+f"(c[1]), "+f"(c[2]), "+f"(c[3])                    \
        : "r"(a[0]), "r"(a[1]), "r"(a[2]), "r"(a[3]), "r"(b0), "r"(b1))

#define MMA_BF16(c, a, b0, b1)                                              \
    asm volatile(                                                           \
        "mma.sync.aligned.m16n8k16.row.col.f32.bf16.bf16.f32 "              \
        "{%0,%1,%2,%3}, {%4,%5,%6,%7}, {%8,%9}, {%0,%1,%2,%3};"             \
        : "+f"(c[0]), "+f"(c[1]), "+f"(c[2]), "+f"(c[3])                    \
        : "r"(a[0]), "r"(a[1]), "r"(a[2]), "r"(a[3]), "r"(b0), "r"(b1))

__device__ __forceinline__ void cp_async16(uint32_t saddr, const void* gptr, int src_bytes) {
    asm volatile("cp.async.cg.shared.global [%0], [%1], 16, %2;\n"
                 :: "r"(saddr), "l"(gptr), "r"(src_bytes));
}
__device__ __forceinline__ void cp_commit() { asm volatile("cp.async.commit_group;\n"); }

__device__ __forceinline__ unsigned pack_h2(float2 p) {
    __half2 h = __float22half2_rn(p);
    return *(unsigned*)&h;
}

// ================= fp16 single-pass pipelined GEMM (att1 / embproj) =================
// Same f32 cp.async staging as before; fragments converted f32->fp16 at LDS time.
// fp16 mantissa == tf32 mantissa (10 bits) => numerically equivalent to tf32 path,
// at half the MMA count (m16n8k16).
#define SROW 36
#define STAGE (128 * SROW + 64 * SROW)

template <typename OutT>
__global__ void __launch_bounds__(256) gemm_f16(
    const float* __restrict__ A, int lda,
    const float* __restrict__ Bm, int ldb,
    const float* __restrict__ bias,
    OutT* __restrict__ C, int ldc,
    int N, int K) {
    extern __shared__ float smem[];
    const int tid = threadIdx.x;
    const int m0 = blockIdx.y * 128;
    const int n0 = blockIdx.x * 64;

    const int warp = tid >> 5, lane = tid & 31;
    const int g = lane >> 2, tg = lane & 3;
    const int wm = (warp >> 1) * 32;
    const int wn = (warp & 1) * 32;

    float acc[2][4][4];
#pragma unroll
    for (int mi = 0; mi < 2; mi++)
#pragma unroll
        for (int ni = 0; ni < 4; ni++)
#pragma unroll
            for (int j = 0; j < 4; j++) acc[mi][ni][j] = 0.f;

    const int ntiles = K >> 5;

    auto load_stage = [&](int buf, int kt) {
        float* sA = smem + buf * STAGE;
        float* sB = sA + 128 * SROW;
#pragma unroll
        for (int i = 0; i < 4; i++) {
            int idx = tid + i * 256;
            int row = idx >> 3;
            int q = (idx & 7) << 2;
            uint32_t d = (uint32_t)__cvta_generic_to_shared(sA + row * SROW + q);
            cp_async16(d, A + (size_t)(m0 + row) * lda + kt + q, 16);
        }
#pragma unroll
        for (int i = 0; i < 2; i++) {
            int idx = tid + i * 256;
            int row = idx >> 3;
            int q = (idx & 7) << 2;
            int nr = n0 + row;
            int ok = (nr < N);
            if (!ok) nr = N - 1;
            uint32_t d = (uint32_t)__cvta_generic_to_shared(sB + row * SROW + q);
            cp_async16(d, Bm + (size_t)nr * ldb + kt + q, ok ? 16 : 0);
        }
        cp_commit();
    };

    load_stage(0, 0);

    for (int kt = 0; kt < ntiles; kt++) {
        if (kt + 1 < ntiles) {
            load_stage((kt + 1) & 1, (kt + 1) << 5);
            asm volatile("cp.async.wait_group 1;\n");
        } else {
            asm volatile("cp.async.wait_group 0;\n");
        }
        __syncthreads();

        const float* sA = smem + (kt & 1) * STAGE;
        const float* sB = sA + 128 * SROW;

#pragma unroll
        for (int ks = 0; ks < 2; ks++) {
            const int k0 = ks * 16;
            unsigned ah[2][4];
#pragma unroll
            for (int mi = 0; mi < 2; mi++) {
                int r = wm + mi * 16;
                ah[mi][0] = pack_h2(*(const float2*)&sA[(r + g) * SROW + k0 + 2 * tg]);
                ah[mi][1] = pack_h2(*(const float2*)&sA[(r + g + 8) * SROW + k0 + 2 * tg]);
                ah[mi][2] = pack_h2(*(const float2*)&sA[(r + g) * SROW + k0 + 8 + 2 * tg]);
                ah[mi][3] = pack_h2(*(const float2*)&sA[(r + g + 8) * SROW + k0 + 8 + 2 * tg]);
            }
#pragma unroll
            for (int ni = 0; ni < 4; ni++) {
                int cb = wn + ni * 8;
                unsigned b0 = pack_h2(*(const float2*)&sB[(cb + g) * SROW + k0 + 2 * tg]);
                unsigned b1 = pack_h2(*(const float2*)&sB[(cb + g) * SROW + k0 + 8 + 2 * tg]);
#pragma unroll
                for (int mi = 0; mi < 2; mi++) MMA_F16(acc[mi][ni], ah[mi], b0, b1);
            }
        }
        __syncthreads();
    }

#pragma unroll
    for (int mi = 0; mi < 2; mi++) {
#pragma unroll
        for (int ni = 0; ni < 4; ni++) {
            int r0 = m0 + wm + mi * 16 + g;
            int c0 = n0 + wn + ni * 8 + tg * 2;
#pragma unroll
            for (int half = 0; half < 2; half++) {
                int rr = r0 + half * 8;
#pragma unroll
                for (int j = 0; j < 2; j++) {
                    int cc = c0 + j;
                    if (cc >= N) continue;
                    float v = acc[mi][ni][half * 2 + j];
                    if (bias) v += bias[cc];
                    C[(size_t)rr * ldc + cc] = (OutT)v;
                }
            }
        }
    }
}

// ================= bf16 hi/lo 3-pass GEMM (precise path) =================
#define PROW 17
#define B16_AH 0
#define B16_AL (128 * PROW)
#define B16_BH (2 * 128 * PROW)
#define B16_BL (2 * 128 * PROW + 64 * PROW)
#define B16_STAGE_U32 (2 * 128 * PROW + 2 * 64 * PROW)   // 6528 u32

__global__ void __launch_bounds__(256) gemm_bf16p(
    const float* __restrict__ A, int lda,
    const float* __restrict__ Bm, int ldb,
    const float* __restrict__ bias,
    const float* __restrict__ Csrc, int ldsrc,
    float* __restrict__ Cbase, int ldc, size_t zstride,
    int N, int K) {
    extern __shared__ uint32_t sm16[];
    const int tid = threadIdx.x;
    const int m0 = blockIdx.y * 128;
    const int n0 = blockIdx.x * 64;
    const int Koff = blockIdx.z * K;
    float* C = Cbase + (size_t)blockIdx.z * zstride;
    const bool final_z = (gridDim.z == 1);

    const int warp = tid >> 5, lane = tid & 31;
    const int g = lane >> 2, tg = lane & 3;
    const int wm = (warp >> 1) * 32;
    const int wn = (warp & 1) * 32;

    float acc[2][4][4];
#pragma unroll
    for (int mi = 0; mi < 2; mi++)
#pragma unroll
        for (int ni = 0; ni < 4; ni++)
#pragma unroll
            for (int j = 0; j < 4; j++) acc[mi][ni][j] = 0.f;

    const int ntiles = K >> 5;
    float4 aR[4];
    float4 bR[2];

    const int a_row = tid >> 3;
    const int a_q = (tid & 7) << 2;
    const int a_p = (tid & 7) << 1;

    auto ldg_tile = [&](int kt) {
        const int kb = Koff + (kt << 5);
#pragma unroll
        for (int i = 0; i < 4; i++) {
            int row = a_row + i * 32;
            aR[i] = *(const float4*)(A + (size_t)(m0 + row) * lda + kb + a_q);
        }
#pragma unroll
        for (int i = 0; i < 2; i++) {
            int row = a_row + i * 32;
            if (n0 + row < N)
                bR[i] = *(const float4*)(Bm + (size_t)(n0 + row) * ldb + kb + a_q);
            else
                bR[i] = make_float4(0.f, 0.f, 0.f, 0.f);
        }
    };

    auto sts_tile = [&](int buf) {
        uint32_t* s = sm16 + buf * B16_STAGE_U32;
#pragma unroll
        for (int i = 0; i < 4; i++) {
            int row = a_row + i * 32;
            const float4 v = aR[i];
            __nv_bfloat162 h0 = __float22bfloat162_rn(make_float2(v.x, v.y));
            __nv_bfloat162 h1 = __float22bfloat162_rn(make_float2(v.z, v.w));
            float2 f0 = __bfloat1622float2(h0);
            float2 f1 = __bfloat1622float2(h1);
            __nv_bfloat162 l0 = __float22bfloat162_rn(make_float2(v.x - f0.x, v.y - f0.y));
            __nv_bfloat162 l1 = __float22bfloat162_rn(make_float2(v.z - f1.x, v.w - f1.y));
            s[B16_AH + row * PROW + a_p] = *(const uint32_t*)&h0;
            s[B16_AH + row * PROW + a_p + 1] = *(const uint32_t*)&h1;
            s[B16_AL + row * PROW + a_p] = *(const uint32_t*)&l0;
            s[B16_AL + row * PROW + a_p + 1] = *(const uint32_t*)&l1;
        }
#pragma unroll
        for (int i = 0; i < 2; i++) {
            int row = a_row + i * 32;
            const float4 v = bR[i];
            __nv_bfloat162 h0 = __float22bfloat162_rn(make_float2(v.x, v.y));
            __nv_bfloat162 h1 = __float22bfloat162_rn(make_float2(v.z, v.w));
            float2 f0 = __bfloat1622float2(h0);
            float2 f1 = __bfloat1622float2(h1);
            __nv_bfloat162 l0 = __float22bfloat162_rn(make_float2(v.x - f0.x, v.y - f0.y));
            __nv_bfloat162 l1 = __float22bfloat162_rn(make_float2(v.z - f1.x, v.w - f1.y));
            s[B16_BH + row * PROW + a_p] = *(const uint32_t*)&h0;
            s[B16_BH + row * PROW + a_p + 1] = *(const uint32_t*)&h1;
            s[B16_BL + row * PROW + a_p] = *(const uint32_t*)&l0;
            s[B16_BL + row * PROW + a_p + 1] = *(const uint32_t*)&l1;
        }
    };

    ldg_tile(0);
    sts_tile(0);
    __syncthreads();

    for (int kt = 0; kt < ntiles; kt++) {
        if (kt + 1 < ntiles) ldg_tile(kt + 1);

        const uint32_t* s = sm16 + (kt & 1) * B16_STAGE_U32;
#pragma unroll
        for (int ks = 0; ks < 2; ks++) {
            const int k0p = ks * 8;
            unsigned ah[2][4], al[2][4];
#pragma unroll
            for (int mi = 0; mi < 2; mi++) {
                int r = wm + mi * 16;
                ah[mi][0] = s[B16_AH + (r + g) * PROW + k0p + tg];
                ah[mi][1] = s[B16_AH + (r + g + 8) * PROW + k0p + tg];
                ah[mi][2] = s[B16_AH + (r + g) * PROW + k0p + 4 + tg];
                ah[mi][3] = s[B16_AH + (r + g + 8) * PROW + k0p + 4 + tg];
                al[mi][0] = s[B16_AL + (r + g) * PROW + k0p + tg];
                al[mi][1] = s[B16_AL + (r + g + 8) * PROW + k0p + tg];
                al[mi][2] = s[B16_AL + (r + g) * PROW + k0p + 4 + tg];
                al[mi][3] = s[B16_AL + (r + g + 8) * PROW + k0p + 4 + tg];
            }
#pragma unroll
            for (int ni = 0; ni < 4; ni++) {
                int cb = wn + ni * 8;
                unsigned bh0 = s[B16_BH + (cb + g) * PROW + k0p + tg];
                unsigned bh1 = s[B16_BH + (cb + g) * PROW + k0p + 4 + tg];
                unsigned bl0 = s[B16_BL + (cb + g) * PROW + k0p + tg];
                unsigned bl1 = s[B16_BL + (cb + g) * PROW + k0p + 4 + tg];
#pragma unroll
                for (int mi = 0; mi < 2; mi++) {
                    MMA_BF16(acc[mi][ni], ah[mi], bh0, bh1);
                    MMA_BF16(acc[mi][ni], al[mi], bh0, bh1);
                    MMA_BF16(acc[mi][ni], ah[mi], bl0, bl1);
                }
            }
        }

        if (kt + 1 < ntiles) {
            __syncthreads();
            sts_tile((kt + 1) & 1);
            __syncthreads();
        }
    }

#pragma unroll
    for (int mi = 0; mi < 2; mi++) {
#pragma unroll
        for (int ni = 0; ni < 4; ni++) {
            int r0 = m0 + wm + mi * 16 + g;
            int c0 = n0 + wn + ni * 8 + tg * 2;
#pragma unroll
            for (int half = 0; half < 2; half++) {
                int rr = r0 + half * 8;
#pragma unroll
                for (int j = 0; j < 2; j++) {
                    int cc = c0 + j;
                    if (cc >= N) continue;
                    float v = acc[mi][ni][half * 2 + j];
                    if (final_z) {
                        if (bias) v += bias[cc];
                        if (Csrc) v += Csrc[(size_t)rr * ldsrc + cc];
                    }
                    C[(size_t)rr * ldc + cc] = v;
                }
            }
        }
    }
}

// ---------------- small kernels ----------------
__global__ void bsum_kernel(float* __restrict__ out, const float* __restrict__ a,
                            const float* __restrict__ b) {
    int i = blockIdx.x * blockDim.x + threadIdx.x;
    if (i < 2048) out[i] = a[i] + b[i];
}

__global__ void gather_kernel(const int* __restrict__ cap, const float* __restrict__ table,
                              float* __restrict__ E) {
    int bt = blockIdx.x;
    int b = bt / TSTEPS, tt = bt % TSTEPS;
    int idx = cap[b * (TSTEPS + 1) + tt];
    const float4* src = (const float4*)(table + (size_t)idx * EMBD);
    float4* dst = (float4*)(E + (size_t)bt * EMBD);
    dst[threadIdx.x] = src[threadIdx.x];
}

// single pass over enc: compute mean AND write fp16 mirror
__global__ void prep_enc_kernel(const float* __restrict__ enc, __half* __restrict__ ench,
                                float* __restrict__ mean) {
    int b = blockIdx.y;
    int e = blockIdx.x * 256 + threadIdx.x;   // 8x256 = 2048
    const float* ep = enc + (size_t)b * RR * ENCD + e;
    __half* op = ench + (size_t)b * RR * ENCD + e;
    float acc = 0.f;
#pragma unroll 4
    for (int r = 0; r < RR; r++) {
        float v = ep[(size_t)r * ENCD];
        acc += v;
        op[(size_t)r * ENCD] = __float2half_rn(v);
    }
    mean[b * ENCD + e] = acc * (1.f / (float)RR);
}

// ============ fused attention + softmax + context + gadd (one block per b) ============
__global__ void __launch_bounds__(1024) att_ctx_kernel(
    const __half2* __restrict__ att1h, const __half2* __restrict__ ench,
    const float* __restrict__ hproj,
    const float* __restrict__ wfull, const float* __restrict__ bfull,
    const float* __restrict__ embproj,
    float* __restrict__ ctx, float* __restrict__ gadd,
    float* __restrict__ out_alpha, int t) {
    int b = blockIdx.x;
    int tid = threadIdx.x;  // 1024
    int warp = tid >> 5, lane = tid & 31;
    __shared__ float s_att2[512], s_wf[512], s_sc[RR], s_red[32];
    if (tid < 512) {
        s_att2[tid] = hproj[b * 4608 + tid];
        s_wf[tid] = wfull[tid];
    }
    __syncthreads();

    // scores: warp per r (32 warps cover 196 rows)
    float bf = bfull[0];
    for (int r = warp; r < RR; r += 32) {
        const __half2* ap = att1h + ((size_t)(b * RR + r)) * (ATTD / 2);
        float s = 0.f;
#pragma unroll 4
        for (int a2 = lane; a2 < ATTD / 2; a2 += 32) {
            float2 f = __half22float2(ap[a2]);
            int a = a2 * 2;
            s += fmaxf(f.x + s_att2[a], 0.f) * s_wf[a]
               + fmaxf(f.y + s_att2[a + 1], 0.f) * s_wf[a + 1];
        }
#pragma unroll
        for (int o = 16; o; o >>= 1) s += __shfl_xor_sync(0xffffffffu, s, o);
        if (lane == 0) s_sc[r] = s + bf;
    }
    __syncthreads();

    // softmax
    float m = -1e30f;
    if (tid < RR) m = s_sc[tid];
#pragma unroll
    for (int o = 16; o; o >>= 1) m = fmaxf(m, __shfl_xor_sync(0xffffffffu, m, o));
    if (lane == 0) s_red[warp] = m;
    __syncthreads();
    m = s_red[0];
#pragma unroll
    for (int w = 1; w < 32; w++) m = fmaxf(m, s_red[w]);
    __syncthreads();
    float sum = 0.f;
    if (tid < RR) {
        float e = expf(s_sc[tid] - m);
        s_sc[tid] = e;
        sum = e;
    }
#pragma unroll
    for (int o = 16; o; o >>= 1) sum += __shfl_xor_sync(0xffffffffu, sum, o);
    if (lane == 0) s_red[warp] = sum;
    __syncthreads();
    sum = 0.f;
#pragma unroll
    for (int w = 0; w < 32; w++) sum += s_red[w];
    float inv = 1.f / sum;
    if (tid < RR) out_alpha[((size_t)b * TSTEPS + t) * RR + tid] = s_sc[tid] * inv;
    __syncthreads();

    // context: thread per e-pair (1024 pairs = 2048 elems)
    int e2 = tid;
    const __half2* ep = ench + (size_t)b * RR * (ENCD / 2) + e2;
    float ax = 0.f, ay = 0.f;
#pragma unroll 4
    for (int r = 0; r < RR; r++) {
        float2 f = __half22float2(ep[(size_t)r * (ENCD / 2)]);
        float a = s_sc[r];
        ax += a * f.x;
        ay += a * f.y;
    }
    ax *= inv;
    ay *= inv;
    int e = e2 * 2;
    float g0 = hproj[b * 4608 + 512 + e];
    float g1 = hproj[b * 4608 + 512 + e + 1];
    ctx[b * ENCD + e]     = ax / (1.f + expf(-g0));
    ctx[b * ENCD + e + 1] = ay / (1.f + expf(-g1));
    const float* ebp = embproj + ((size_t)b * TSTEPS + t) * 2048;
    gadd[b * 2048 + e]     = ebp[e] + hproj[b * 4608 + 2560 + e];
    gadd[b * 2048 + e + 1] = ebp[e + 1] + hproj[b * 4608 + 2560 + e + 1];
}

// sums 4 split-K partials + gadd, LSTM pointwise, writes h to state AND g_H[t]
__global__ void lstm_kernel(const float* __restrict__ gpart, const float* __restrict__ gadd,
                            float* __restrict__ state, float* __restrict__ Hout, int t) {
    int b = blockIdx.x, d = threadIdx.x;  // 512 threads
    float gt[4];
#pragma unroll
    for (int q = 0; q < 4; q++) {
        int j = b * 2048 + q * 512 + d;
        float s = gadd[j];
#pragma unroll
        for (int z = 0; z < 4; z++) s += gpart[z * BATCH * 2048 + j];
        gt[q] = s;
    }
    float i_ = 1.f / (1.f + expf(-gt[0]));
    float f_ = 1.f / (1.f + expf(-gt[1]));
    float g_ = tanhf(gt[2]);
    float o_ = 1.f / (1.f + expf(-gt[3]));
    float c = state[b * 1024 + 512 + d];
    float cn = f_ * c + i_ * g_;
    float hn = o_ * tanhf(cn);
    state[b * 1024 + d] = hn;
    state[b * 1024 + 512 + d] = cn;
    Hout[((size_t)b * TSTEPS + t) * DECD + d] = hn;
}

// ---------------- host ----------------
static float* symaddr(const void* sym) {
    void* p = nullptr;
    cudaGetSymbolAddress(&p, sym);
    return (float*)p;
}

static const int F16_SMEM = 2 * STAGE * 4;
static const int BF16_SMEM = 2 * B16_STAGE_U32 * 4;

template <typename OutT>
static void launch_f16(const float* A, int lda, const float* B, int ldb,
                       const float* bias, OutT* C, int ldc, int M, int N, int K) {
    dim3 grid((N + 63) / 64, M / 128, 1);
    gemm_f16<OutT><<<grid, 256, F16_SMEM>>>(A, lda, B, ldb, bias, C, ldc, N, K);
}

static void launch_bf16p(const float* A, int lda, const float* B, int ldb,
                         const float* bias, const float* Csrc, int ldsrc, float* C, int ldc,
                         size_t zstride, int M, int N, int K, int zsplit) {
    dim3 grid((N + 63) / 64, M / 128, zsplit);
    gemm_bf16p<<<grid, 256, BF16_SMEM>>>(A, lda, B, ldb, bias, Csrc, ldsrc, C, ldc,
                                         zstride, N, K / zsplit);
}

extern "C" void kernel_launch(void* const* d_in, const int* in_sizes, int n_in,
                              void* d_out, int out_size) {
    const float* enc       = (const float*)d_in[0];
    const int*   captions  = (const int*)d_in[1];
    const float* W_enc_att = (const float*)d_in[2];
    const float* b_enc_att = (const float*)d_in[3];
    const float* W_dec_att = (const float*)d_in[4];
    const float* b_dec_att = (const float*)d_in[5];
    const float* W_full    = (const float*)d_in[6];
    const float* b_full    = (const float*)d_in[7];
    const float* emb_table = (const float*)d_in[8];
    const float* W_ih      = (const float*)d_in[9];
    const float* W_hh      = (const float*)d_in[10];
    const float* b_ih      = (const float*)d_in[11];
    const float* b_hh      = (const float*)d_in[12];
    const float* W_init_h  = (const float*)d_in[13];
    const float* b_init_h  = (const float*)d_in[14];
    const float* W_init_c  = (const float*)d_in[15];
    const float* b_init_c  = (const float*)d_in[16];
    const float* W_fbeta   = (const float*)d_in[17];
    const float* b_fbeta   = (const float*)d_in[18];
    const float* W_fc      = (const float*)d_in[19];
    const float* b_fc      = (const float*)d_in[20];

    float* out_pred  = (float*)d_out;
    float* out_alpha = out_pred + (size_t)BATCH * TSTEPS * VOC;

    __half* att1h = (__half*)symaddr(g_att1h);
    __half* ench  = (__half*)symaddr(g_ench);
    float* meanb  = symaddr(g_mean);
    float* state  = symaddr(g_state);
    float* hproj  = symaddr(g_hproj);
    float* ctx    = symaddr(g_ctx);
    float* gadd   = symaddr(g_gadd);
    float* gpart  = symaddr(g_gpart);
    float* Hbuf   = symaddr(g_H);
    float* E      = symaddr(g_E);
    float* embprj = symaddr(g_embproj);
    float* Wcat   = symaddr(g_Wcat);
    float* bcat   = symaddr(g_bcat);
    float* bsum   = symaddr(g_bsum);
    float* Winit  = symaddr(g_Winit);
    float* binit  = symaddr(g_binit);

    cudaFuncSetAttribute(gemm_f16<float>, cudaFuncAttributeMaxDynamicSharedMemorySize, F16_SMEM);
    cudaFuncSetAttribute(gemm_f16<__half>, cudaFuncAttributeMaxDynamicSharedMemorySize, F16_SMEM);
    cudaFuncSetAttribute(gemm_bf16p, cudaFuncAttributeMaxDynamicSharedMemorySize, BF16_SMEM);

    // ---- prologue: weight concats ----
    cudaMemcpyAsync(Wcat, W_dec_att, (size_t)512 * 512 * 4, cudaMemcpyDeviceToDevice, 0);
    cudaMemcpyAsync(Wcat + 512 * 512, W_fbeta, (size_t)2048 * 512 * 4, cudaMemcpyDeviceToDevice, 0);
    cudaMemcpyAsync(Wcat + 2560 * 512, W_hh, (size_t)2048 * 512 * 4, cudaMemcpyDeviceToDevice, 0);
    cudaMemcpyAsync(bcat, b_dec_att, 512 * 4, cudaMemcpyDeviceToDevice, 0);
    cudaMemcpyAsync(bcat + 512, b_fbeta, 2048 * 4, cudaMemcpyDeviceToDevice, 0);
    cudaMemsetAsync(bcat + 2560, 0, 2048 * 4, 0);
    cudaMemcpyAsync(Winit, W_init_h, (size_t)512 * 2048 * 4, cudaMemcpyDeviceToDevice, 0);
    cudaMemcpyAsync(Winit + (size_t)512 * 2048, W_init_c, (size_t)512 * 2048 * 4,
                    cudaMemcpyDeviceToDevice, 0);
    cudaMemcpyAsync(binit, b_init_h, 512 * 4, cudaMemcpyDeviceToDevice, 0);
    cudaMemcpyAsync(binit + 512, b_init_c, 512 * 4, cudaMemcpyDeviceToDevice, 0);

    bsum_kernel<<<8, 256>>>(bsum, b_ih, b_hh);
    // one pass over enc: mean + fp16 mirror
    prep_enc_kernel<<<dim3(8, BATCH), 256>>>(enc, ench, meanb);
    // state = mean @ [W_init_h; W_init_c]^T + [b_init_h; b_init_c]
    launch_bf16p(meanb, ENCD, Winit, ENCD, binit, nullptr, 0, state, 1024, 0,
                 BATCH, 1024, ENCD, 1);
    gather_kernel<<<BATCH * TSTEPS, 128>>>(captions, emb_table, E);
    // embproj (all t): E @ W_ih[:, :512]^T + (b_ih + b_hh)   (fp16 1-pass, ~tf32 numerics)
    launch_f16<float>(E, EMBD, W_ih, EMBD + ENCD, bsum, embprj, 2048, BATCH * TSTEPS, 2048, EMBD);
    // att1 = enc @ W_enc_att^T + b_enc_att   (fp16 1-pass, fp16 output)
    launch_f16<__half>(enc, ENCD, W_enc_att, ENCD, b_enc_att, att1h, ATTD, BATCH * RR, ATTD, ENCD);

    // ---- recurrence (fc hoisted) ----
    for (int t = 0; t < TSTEPS; t++) {
        // hproj = h @ [W_dec_att; W_fbeta; W_hh]^T + [b_dec_att; b_fbeta; 0]
        launch_bf16p(state, 1024, Wcat, 512, bcat, nullptr, 0, hproj, 4608, 0,
                     BATCH, 4608, DECD, 1);
        att_ctx_kernel<<<BATCH, 1024>>>((const __half2*)att1h, (const __half2*)ench, hproj,
                                        W_full, b_full, embprj, ctx, gadd, out_alpha, t);
        // gates partials = ctx @ W_ih[:, 512:]^T   (split-K = 4)
        launch_bf16p(ctx, ENCD, W_ih + 512, EMBD + ENCD, nullptr, nullptr, 0, gpart, 2048,
                     (size_t)BATCH * 2048, BATCH, 2048, ENCD, 4);
        lstm_kernel<<<BATCH, 512>>>(gpart, gadd, state, Hbuf, t);
    }

    // ---- batched fc: preds[b,t,:] = h_t @ W_fc^T + b_fc ----
    launch_bf16p(Hbuf, DECD, W_fc, DECD, b_fc, nullptr, 0, out_pred, VOC, 0,
                 BATCH * TSTEPS, VOC, DECD, 1);
}

// round 10
// speedup vs baseline: 3.3959x; 1.0970x over previous
#include <cuda_runtime.h>
#include <cuda_fp16.h>
#include <cstdint>
#include <cstddef>

#define BATCH 128
#define RR    196
#define ENCD  2048
#define ATTD  512
#define DECD  512
#define EMBD  512
#define VOC   10000
#define TSTEPS 20

// ---------------- device scratch (static allocation only) ----------------
__device__ __half g_att1h[(size_t)BATCH * RR * ATTD];   // fp16 att1 (25.7 MB)
__device__ __half g_ench[(size_t)BATCH * RR * ENCD];    // fp16 mirror of enc (102.8 MB)
__device__ float g_mean[BATCH * ENCD];
__device__ float g_state[BATCH * 1024];            // [h | c]
__device__ float g_hproj[BATCH * 4608];            // [att2 | fbeta_pre | hWhh]
__device__ float g_ctx[BATCH * ENCD];
__device__ float g_gadd[BATCH * 2048];
__device__ float g_gpart[4 * BATCH * 2048];        // split-K partials for gates
__device__ float g_H[BATCH * TSTEPS * DECD];       // all h_t, row = b*TSTEPS+t
__device__ float g_E[BATCH * TSTEPS * EMBD];
__device__ float g_embproj[BATCH * TSTEPS * 2048];
__device__ float g_Wcat[4608 * 512];
__device__ float g_bcat[4608];
__device__ float g_bsum[2048];
__device__ float g_Winit[1024 * ENCD];
__device__ float g_binit[1024];

// ---------------- helpers ----------------
#define MMA_F16(c, a, b0, b1)                                               \
    asm volatile(                                                           \
        "mma.sync.aligned.m16n8k16.row.col.f32.f16.f16.f32 "                \
        "{%0,%1,%2,%3}, {%4,%5,%6,%7}, {%8,%9}, {%0,%1,%2,%3};"             \
        : "+f"(c[0]), "+f"(c[1]), "+f"(c[2]), "+f"(c[3])                    \
        : "r"(a[0]), "r"(a[1]), "r"(a[2]), "r"(a[3]), "r"(b0), "r"(b1))

__device__ __forceinline__ void cp_async16(uint32_t saddr, const void* gptr, int src_bytes) {
    asm volatile("cp.async.cg.shared.global [%0], [%1], 16, %2;\n"
                 :: "r"(saddr), "l"(gptr), "r"(src_bytes));
}
__device__ __forceinline__ void cp_commit() { asm volatile("cp.async.commit_group;\n"); }

__device__ __forceinline__ unsigned pack_h2(float2 p) {
    __half2 h = __float22half2_rn(p);
    return *(unsigned*)&h;
}

// ================= fp16 single-pass pipelined GEMM (unified) =================
// C[M,N](z) = A[M, Koff+K] slice @ B^T (+bias) (+Csrc) ; BM=128, BN=64, BK=32.
// 256 threads, cp.async double buffer, f32 staging, f32->fp16 at fragment load.
// fp16 mantissa == tf32 mantissa (10 bits): tf32-class numerics at half the MMAs.
#define SROW 36
#define STAGE (128 * SROW + 64 * SROW)

template <typename OutT>
__global__ void __launch_bounds__(256) gemm_f16(
    const float* __restrict__ A, int lda,
    const float* __restrict__ Bm, int ldb,
    const float* __restrict__ bias,
    const float* __restrict__ Csrc, int ldsrc,
    OutT* __restrict__ Cbase, int ldc, size_t zstride,
    int N, int K) {
    extern __shared__ float smem[];
    const int tid = threadIdx.x;
    const int m0 = blockIdx.y * 128;
    const int n0 = blockIdx.x * 64;
    const int Koff = blockIdx.z * K;
    OutT* C = Cbase + (size_t)blockIdx.z * zstride;
    const bool final_z = (gridDim.z == 1);

    const int warp = tid >> 5, lane = tid & 31;
    const int g = lane >> 2, tg = lane & 3;
    const int wm = (warp >> 1) * 32;
    const int wn = (warp & 1) * 32;

    float acc[2][4][4];
#pragma unroll
    for (int mi = 0; mi < 2; mi++)
#pragma unroll
        for (int ni = 0; ni < 4; ni++)
#pragma unroll
            for (int j = 0; j < 4; j++) acc[mi][ni][j] = 0.f;

    const int ntiles = K >> 5;

    auto load_stage = [&](int buf, int kt) {
        float* sA = smem + buf * STAGE;
        float* sB = sA + 128 * SROW;
        const int kb = Koff + kt;
#pragma unroll
        for (int i = 0; i < 4; i++) {
            int idx = tid + i * 256;
            int row = idx >> 3;
            int q = (idx & 7) << 2;
            uint32_t d = (uint32_t)__cvta_generic_to_shared(sA + row * SROW + q);
            cp_async16(d, A + (size_t)(m0 + row) * lda + kb + q, 16);
        }
#pragma unroll
        for (int i = 0; i < 2; i++) {
            int idx = tid + i * 256;
            int row = idx >> 3;
            int q = (idx & 7) << 2;
            int nr = n0 + row;
            int ok = (nr < N);
            if (!ok) nr = N - 1;
            uint32_t d = (uint32_t)__cvta_generic_to_shared(sB + row * SROW + q);
            cp_async16(d, Bm + (size_t)nr * ldb + kb + q, ok ? 16 : 0);
        }
        cp_commit();
    };

    load_stage(0, 0);

    for (int kt = 0; kt < ntiles; kt++) {
        if (kt + 1 < ntiles) {
            load_stage((kt + 1) & 1, (kt + 1) << 5);
            asm volatile("cp.async.wait_group 1;\n");
        } else {
            asm volatile("cp.async.wait_group 0;\n");
        }
        __syncthreads();

        const float* sA = smem + (kt & 1) * STAGE;
        const float* sB = sA + 128 * SROW;

#pragma unroll
        for (int ks = 0; ks < 2; ks++) {
            const int k0 = ks * 16;
            unsigned ah[2][4];
#pragma unroll
            for (int mi = 0; mi < 2; mi++) {
                int r = wm + mi * 16;
                ah[mi][0] = pack_h2(*(const float2*)&sA[(r + g) * SROW + k0 + 2 * tg]);
                ah[mi][1] = pack_h2(*(const float2*)&sA[(r + g + 8) * SROW + k0 + 2 * tg]);
                ah[mi][2] = pack_h2(*(const float2*)&sA[(r + g) * SROW + k0 + 8 + 2 * tg]);
                ah[mi][3] = pack_h2(*(const float2*)&sA[(r + g + 8) * SROW + k0 + 8 + 2 * tg]);
            }
#pragma unroll
            for (int ni = 0; ni < 4; ni++) {
                int cb = wn + ni * 8;
                unsigned b0 = pack_h2(*(const float2*)&sB[(cb + g) * SROW + k0 + 2 * tg]);
                unsigned b1 = pack_h2(*(const float2*)&sB[(cb + g) * SROW + k0 + 8 + 2 * tg]);
#pragma unroll
                for (int mi = 0; mi < 2; mi++) MMA_F16(acc[mi][ni], ah[mi], b0, b1);
            }
        }
        __syncthreads();
    }

#pragma unroll
    for (int mi = 0; mi < 2; mi++) {
#pragma unroll
        for (int ni = 0; ni < 4; ni++) {
            int r0 = m0 + wm + mi * 16 + g;
            int c0 = n0 + wn + ni * 8 + tg * 2;
#pragma unroll
            for (int half = 0; half < 2; half++) {
                int rr = r0 + half * 8;
#pragma unroll
                for (int j = 0; j < 2; j++) {
                    int cc = c0 + j;
                    if (cc >= N) continue;
                    float v = acc[mi][ni][half * 2 + j];
                    if (final_z) {
                        if (bias) v += bias[cc];
                        if (Csrc) v += Csrc[(size_t)rr * ldsrc + cc];
                    }
                    C[(size_t)rr * ldc + cc] = (OutT)v;
                }
            }
        }
    }
}

// ---------------- small kernels ----------------
__global__ void bsum_kernel(float* __restrict__ out, const float* __restrict__ a,
                            const float* __restrict__ b) {
    int i = blockIdx.x * blockDim.x + threadIdx.x;
    if (i < 2048) out[i] = a[i] + b[i];
}

__global__ void gather_kernel(const int* __restrict__ cap, const float* __restrict__ table,
                              float* __restrict__ E) {
    int bt = blockIdx.x;
    int b = bt / TSTEPS, tt = bt % TSTEPS;
    int idx = cap[b * (TSTEPS + 1) + tt];
    const float4* src = (const float4*)(table + (size_t)idx * EMBD);
    float4* dst = (float4*)(E + (size_t)bt * EMBD);
    dst[threadIdx.x] = src[threadIdx.x];
}

// single pass over enc: compute mean AND write fp16 mirror
__global__ void prep_enc_kernel(const float* __restrict__ enc, __half* __restrict__ ench,
                                float* __restrict__ mean) {
    int b = blockIdx.y;
    int e = blockIdx.x * 256 + threadIdx.x;   // 8x256 = 2048
    const float* ep = enc + (size_t)b * RR * ENCD + e;
    __half* op = ench + (size_t)b * RR * ENCD + e;
    float acc = 0.f;
#pragma unroll 4
    for (int r = 0; r < RR; r++) {
        float v = ep[(size_t)r * ENCD];
        acc += v;
        op[(size_t)r * ENCD] = __float2half_rn(v);
    }
    mean[b * ENCD + e] = acc * (1.f / (float)RR);
}

// ============ fused attention + softmax + context + gadd (one block per b) ============
__global__ void __launch_bounds__(1024) att_ctx_kernel(
    const __half2* __restrict__ att1h, const __half2* __restrict__ ench,
    const float* __restrict__ hproj,
    const float* __restrict__ wfull, const float* __restrict__ bfull,
    const float* __restrict__ embproj,
    float* __restrict__ ctx, float* __restrict__ gadd,
    float* __restrict__ out_alpha, int t) {
    int b = blockIdx.x;
    int tid = threadIdx.x;  // 1024
    int warp = tid >> 5, lane = tid & 31;
    __shared__ float s_att2[512], s_wf[512], s_sc[RR], s_red[32];
    if (tid < 512) {
        s_att2[tid] = hproj[b * 4608 + tid];
        s_wf[tid] = wfull[tid];
    }
    __syncthreads();

    float bf = bfull[0];
    for (int r = warp; r < RR; r += 32) {
        const __half2* ap = att1h + ((size_t)(b * RR + r)) * (ATTD / 2);
        float s = 0.f;
#pragma unroll 4
        for (int a2 = lane; a2 < ATTD / 2; a2 += 32) {
            float2 f = __half22float2(ap[a2]);
            int a = a2 * 2;
            s += fmaxf(f.x + s_att2[a], 0.f) * s_wf[a]
               + fmaxf(f.y + s_att2[a + 1], 0.f) * s_wf[a + 1];
        }
#pragma unroll
        for (int o = 16; o; o >>= 1) s += __shfl_xor_sync(0xffffffffu, s, o);
        if (lane == 0) s_sc[r] = s + bf;
    }
    __syncthreads();

    float m = -1e30f;
    if (tid < RR) m = s_sc[tid];
#pragma unroll
    for (int o = 16; o; o >>= 1) m = fmaxf(m, __shfl_xor_sync(0xffffffffu, m, o));
    if (lane == 0) s_red[warp] = m;
    __syncthreads();
    m = s_red[0];
#pragma unroll
    for (int w = 1; w < 32; w++) m = fmaxf(m, s_red[w]);
    __syncthreads();
    float sum = 0.f;
    if (tid < RR) {
        float e = expf(s_sc[tid] - m);
        s_sc[tid] = e;
        sum = e;
    }
#pragma unroll
    for (int o = 16; o; o >>= 1) sum += __shfl_xor_sync(0xffffffffu, sum, o);
    if (lane == 0) s_red[warp] = sum;
    __syncthreads();
    sum = 0.f;
#pragma unroll
    for (int w = 0; w < 32; w++) sum += s_red[w];
    float inv = 1.f / sum;
    if (tid < RR) out_alpha[((size_t)b * TSTEPS + t) * RR + tid] = s_sc[tid] * inv;
    __syncthreads();

    int e2 = tid;
    const __half2* ep = ench + (size_t)b * RR * (ENCD / 2) + e2;
    float ax = 0.f, ay = 0.f;
#pragma unroll 4
    for (int r = 0; r < RR; r++) {
        float2 f = __half22float2(ep[(size_t)r * (ENCD / 2)]);
        float a = s_sc[r];
        ax += a * f.x;
        ay += a * f.y;
    }
    ax *= inv;
    ay *= inv;
    int e = e2 * 2;
    float g0 = hproj[b * 4608 + 512 + e];
    float g1 = hproj[b * 4608 + 512 + e + 1];
    ctx[b * ENCD + e]     = ax / (1.f + expf(-g0));
    ctx[b * ENCD + e + 1] = ay / (1.f + expf(-g1));
    const float* ebp = embproj + ((size_t)b * TSTEPS + t) * 2048;
    gadd[b * 2048 + e]     = ebp[e] + hproj[b * 4608 + 2560 + e];
    gadd[b * 2048 + e + 1] = ebp[e + 1] + hproj[b * 4608 + 2560 + e + 1];
}

// sums 4 split-K partials + gadd, LSTM pointwise, writes h to state AND g_H[t]
__global__ void lstm_kernel(const float* __restrict__ gpart, const float* __restrict__ gadd,
                            float* __restrict__ state, float* __restrict__ Hout, int t) {
    int b = blockIdx.x, d = threadIdx.x;  // 512 threads
    float gt[4];
#pragma unroll
    for (int q = 0; q < 4; q++) {
        int j = b * 2048 + q * 512 + d;
        float s = gadd[j];
#pragma unroll
        for (int z = 0; z < 4; z++) s += gpart[z * BATCH * 2048 + j];
        gt[q] = s;
    }
    float i_ = 1.f / (1.f + expf(-gt[0]));
    float f_ = 1.f / (1.f + expf(-gt[1]));
    float g_ = tanhf(gt[2]);
    float o_ = 1.f / (1.f + expf(-gt[3]));
    float c = state[b * 1024 + 512 + d];
    float cn = f_ * c + i_ * g_;
    float hn = o_ * tanhf(cn);
    state[b * 1024 + d] = hn;
    state[b * 1024 + 512 + d] = cn;
    Hout[((size_t)b * TSTEPS + t) * DECD + d] = hn;
}

// ---------------- host ----------------
static float* symaddr(const void* sym) {
    void* p = nullptr;
    cudaGetSymbolAddress(&p, sym);
    return (float*)p;
}

static const int F16_SMEM = 2 * STAGE * 4;

template <typename OutT>
static void launch_f16(const float* A, int lda, const float* B, int ldb,
                       const float* bias, const float* Csrc, int ldsrc,
                       OutT* C, int ldc, size_t zstride,
                       int M, int N, int K, int zsplit) {
    dim3 grid((N + 63) / 64, M / 128, zsplit);
    gemm_f16<OutT><<<grid, 256, F16_SMEM>>>(A, lda, B, ldb, bias, Csrc, ldsrc, C, ldc,
                                            zstride, N, K / zsplit);
}

extern "C" void kernel_launch(void* const* d_in, const int* in_sizes, int n_in,
                              void* d_out, int out_size) {
    const float* enc       = (const float*)d_in[0];
    const int*   captions  = (const int*)d_in[1];
    const float* W_enc_att = (const float*)d_in[2];
    const float* b_enc_att = (const float*)d_in[3];
    const float* W_dec_att = (const float*)d_in[4];
    const float* b_dec_att = (const float*)d_in[5];
    const float* W_full    = (const float*)d_in[6];
    const float* b_full    = (const float*)d_in[7];
    const float* emb_table = (const float*)d_in[8];
    const float* W_ih      = (const float*)d_in[9];
    const float* W_hh      = (const float*)d_in[10];
    const float* b_ih      = (const float*)d_in[11];
    const float* b_hh      = (const float*)d_in[12];
    const float* W_init_h  = (const float*)d_in[13];
    const float* b_init_h  = (const float*)d_in[14];
    const float* W_init_c  = (const float*)d_in[15];
    const float* b_init_c  = (const float*)d_in[16];
    const float* W_fbeta   = (const float*)d_in[17];
    const float* b_fbeta   = (const float*)d_in[18];
    const float* W_fc      = (const float*)d_in[19];
    const float* b_fc      = (const float*)d_in[20];

    float* out_pred  = (float*)d_out;
    float* out_alpha = out_pred + (size_t)BATCH * TSTEPS * VOC;

    __half* att1h = (__half*)symaddr(g_att1h);
    __half* ench  = (__half*)symaddr(g_ench);
    float* meanb  = symaddr(g_mean);
    float* state  = symaddr(g_state);
    float* hproj  = symaddr(g_hproj);
    float* ctx    = symaddr(g_ctx);
    float* gadd   = symaddr(g_gadd);
    float* gpart  = symaddr(g_gpart);
    float* Hbuf   = symaddr(g_H);
    float* E      = symaddr(g_E);
    float* embprj = symaddr(g_embproj);
    float* Wcat   = symaddr(g_Wcat);
    float* bcat   = symaddr(g_bcat);
    float* bsum   = symaddr(g_bsum);
    float* Winit  = symaddr(g_Winit);
    float* binit  = symaddr(g_binit);

    cudaFuncSetAttribute(gemm_f16<float>, cudaFuncAttributeMaxDynamicSharedMemorySize, F16_SMEM);
    cudaFuncSetAttribute(gemm_f16<__half>, cudaFuncAttributeMaxDynamicSharedMemorySize, F16_SMEM);

    // ---- prologue: weight concats ----
    cudaMemcpyAsync(Wcat, W_dec_att, (size_t)512 * 512 * 4, cudaMemcpyDeviceToDevice, 0);
    cudaMemcpyAsync(Wcat + 512 * 512, W_fbeta, (size_t)2048 * 512 * 4, cudaMemcpyDeviceToDevice, 0);
    cudaMemcpyAsync(Wcat + 2560 * 512, W_hh, (size_t)2048 * 512 * 4, cudaMemcpyDeviceToDevice, 0);
    cudaMemcpyAsync(bcat, b_dec_att, 512 * 4, cudaMemcpyDeviceToDevice, 0);
    cudaMemcpyAsync(bcat + 512, b_fbeta, 2048 * 4, cudaMemcpyDeviceToDevice, 0);
    cudaMemsetAsync(bcat + 2560, 0, 2048 * 4, 0);
    cudaMemcpyAsync(Winit, W_init_h, (size_t)512 * 2048 * 4, cudaMemcpyDeviceToDevice, 0);
    cudaMemcpyAsync(Winit + (size_t)512 * 2048, W_init_c, (size_t)512 * 2048 * 4,
                    cudaMemcpyDeviceToDevice, 0);
    cudaMemcpyAsync(binit, b_init_h, 512 * 4, cudaMemcpyDeviceToDevice, 0);
    cudaMemcpyAsync(binit + 512, b_init_c, 512 * 4, cudaMemcpyDeviceToDevice, 0);

    bsum_kernel<<<8, 256>>>(bsum, b_ih, b_hh);
    // one pass over enc: mean + fp16 mirror
    prep_enc_kernel<<<dim3(8, BATCH), 256>>>(enc, ench, meanb);
    // state = mean @ [W_init_h; W_init_c]^T + [b_init_h; b_init_c]
    launch_f16<float>(meanb, ENCD, Winit, ENCD, binit, nullptr, 0, state, 1024, 0,
                      BATCH, 1024, ENCD, 1);
    gather_kernel<<<BATCH * TSTEPS, 128>>>(captions, emb_table, E);
    // embproj (all t): E @ W_ih[:, :512]^T + (b_ih + b_hh)
    launch_f16<float>(E, EMBD, W_ih, EMBD + ENCD, bsum, nullptr, 0, embprj, 2048, 0,
                      BATCH * TSTEPS, 2048, EMBD, 1);
    // att1 = enc @ W_enc_att^T + b_enc_att (fp16 output)
    launch_f16<__half>(enc, ENCD, W_enc_att, ENCD, b_enc_att, nullptr, 0, att1h, ATTD, 0,
                       BATCH * RR, ATTD, ENCD, 1);

    // ---- recurrence (fc hoisted) ----
    for (int t = 0; t < TSTEPS; t++) {
        // hproj = h @ [W_dec_att; W_fbeta; W_hh]^T + [b_dec_att; b_fbeta; 0]
        launch_f16<float>(state, 1024, Wcat, 512, bcat, nullptr, 0, hproj, 4608, 0,
                          BATCH, 4608, DECD, 1);
        att_ctx_kernel<<<BATCH, 1024>>>((const __half2*)att1h, (const __half2*)ench, hproj,
                                        W_full, b_full, embprj, ctx, gadd, out_alpha, t);
        // gates partials = ctx @ W_ih[:, 512:]^T   (split-K = 4)
        launch_f16<float>(ctx, ENCD, W_ih + 512, EMBD + ENCD, nullptr, nullptr, 0, gpart, 2048,
                          (size_t)BATCH * 2048, BATCH, 2048, ENCD, 4);
        lstm_kernel<<<BATCH, 512>>>(gpart, gadd, state, Hbuf, t);
    }

    // ---- batched fc: preds[b,t,:] = h_t @ W_fc^T + b_fc ----
    launch_f16<float>(Hbuf, DECD, W_fc, DECD, b_fc, nullptr, 0, out_pred, VOC, 0,
                      BATCH * TSTEPS, VOC, DECD, 1);
}

// round 11
// speedup vs baseline: 4.1190x; 1.2129x over previous
#include <cuda_runtime.h>
#include <cuda_fp16.h>
#include <cstdint>
#include <cstddef>

#define BATCH 128
#define RR    196
#define ENCD  2048
#define ATTD  512
#define DECD  512
#define EMBD  512
#define VOC   10000
#define TSTEPS 20

// ---------------- device scratch (static allocation only) ----------------
__device__ __half g_att1h[(size_t)BATCH * RR * ATTD];   // fp16 att1 (25.7 MB)
__device__ __half g_ench[(size_t)BATCH * RR * ENCD];    // fp16 mirror of enc (102.8 MB)
__device__ float g_mean[BATCH * ENCD];
__device__ float g_state[BATCH * 1024];            // [h | c]
__device__ float g_hproj[BATCH * 4608];            // [att2 | fbeta_pre | hWhh]
__device__ float g_ctx[BATCH * ENCD];
__device__ float g_gadd[BATCH * 2048];
__device__ float g_gpart[4 * BATCH * 2048];        // split-K partials for gates
__device__ float g_H[BATCH * TSTEPS * DECD];       // all h_t, row = b*TSTEPS+t
__device__ float g_E[BATCH * TSTEPS * EMBD];
__device__ float g_embproj[BATCH * TSTEPS * 2048];
__device__ float g_Wcat[4608 * 512];
__device__ float g_bcat[4608];
__device__ float g_bsum[2048];
__device__ float g_Winit[1024 * ENCD];
__device__ float g_binit[1024];

// ---------------- helpers ----------------
#define MMA_F16(c, a, b0, b1)                                               \
    asm volatile(                                                           \
        "mma.sync.aligned.m16n8k16.row.col.f32.f16.f16.f32 "                \
        "{%0,%1,%2,%3}, {%4,%5,%6,%7}, {%8,%9}, {%0,%1,%2,%3};"             \
        : "+f"(c[0]), "+f"(c[1]), "+f"(c[2]), "+f"(c[3])                    \
        : "r"(a[0]), "r"(a[1]), "r"(a[2]), "r"(a[3]), "r"(b0), "r"(b1))

__device__ __forceinline__ void cp_async16(uint32_t saddr, const void* gptr, int src_bytes) {
    asm volatile("cp.async.cg.shared.global [%0], [%1], 16, %2;\n"
                 :: "r"(saddr), "l"(gptr), "r"(src_bytes));
}
__device__ __forceinline__ void cp_commit() { asm volatile("cp.async.commit_group;\n"); }

__device__ __forceinline__ unsigned pack_h2(float2 p) {
    __half2 h = __float22half2_rn(p);
    return *(unsigned*)&h;
}

// ================= fp16 single-pass pipelined GEMM (tiled BN=64 or 128) =================
// C[M,N](z) = A[M, Koff+K] @ B^T (+bias) (+Csrc). BM=128, BK=32, 256 threads,
// cp.async double-buffered f32 staging, f32->fp16 at fragment load.
#define SROW 36

template <int BN, typename OutT>
__global__ void __launch_bounds__(256) gemm_f16(
    const float* __restrict__ A, int lda,
    const float* __restrict__ Bm, int ldb,
    const float* __restrict__ bias,
    const float* __restrict__ Csrc, int ldsrc,
    OutT* __restrict__ Cbase, int ldc, size_t zstride,
    int N, int K) {
    constexpr int STAGE_T = (128 + BN) * SROW;
    constexpr int NI = BN / 16;          // n-fragments per warp (4 or 8)
    extern __shared__ float smem[];
    const int tid = threadIdx.x;
    const int m0 = blockIdx.y * 128;
    const int n0 = blockIdx.x * BN;
    const int Koff = blockIdx.z * K;
    OutT* C = Cbase + (size_t)blockIdx.z * zstride;
    const bool final_z = (gridDim.z == 1);

    const int warp = tid >> 5, lane = tid & 31;
    const int g = lane >> 2, tg = lane & 3;
    const int wm = (warp >> 1) * 32;
    const int wn = (warp & 1) * (BN / 2);

    float acc[2][NI][4];
#pragma unroll
    for (int mi = 0; mi < 2; mi++)
#pragma unroll
        for (int ni = 0; ni < NI; ni++)
#pragma unroll
            for (int j = 0; j < 4; j++) acc[mi][ni][j] = 0.f;

    const int ntiles = K >> 5;

    auto load_stage = [&](int buf, int kt) {
        float* sA = smem + buf * STAGE_T;
        float* sB = sA + 128 * SROW;
        const int kb = Koff + kt;
#pragma unroll
        for (int i = 0; i < 4; i++) {
            int idx = tid + i * 256;
            int row = idx >> 3;
            int q = (idx & 7) << 2;
            uint32_t d = (uint32_t)__cvta_generic_to_shared(sA + row * SROW + q);
            cp_async16(d, A + (size_t)(m0 + row) * lda + kb + q, 16);
        }
#pragma unroll
        for (int i = 0; i < BN / 32; i++) {
            int idx = tid + i * 256;
            int row = idx >> 3;
            int q = (idx & 7) << 2;
            int nr = n0 + row;
            int ok = (nr < N);
            if (!ok) nr = N - 1;
            uint32_t d = (uint32_t)__cvta_generic_to_shared(sB + row * SROW + q);
            cp_async16(d, Bm + (size_t)nr * ldb + kb + q, ok ? 16 : 0);
        }
        cp_commit();
    };

    load_stage(0, 0);

    for (int kt = 0; kt < ntiles; kt++) {
        if (kt + 1 < ntiles) {
            load_stage((kt + 1) & 1, (kt + 1) << 5);
            asm volatile("cp.async.wait_group 1;\n");
        } else {
            asm volatile("cp.async.wait_group 0;\n");
        }
        __syncthreads();

        const float* sA = smem + (kt & 1) * STAGE_T;
        const float* sB = sA + 128 * SROW;

#pragma unroll
        for (int ks = 0; ks < 2; ks++) {
            const int k0 = ks * 16;
            unsigned ah[2][4];
#pragma unroll
            for (int mi = 0; mi < 2; mi++) {
                int r = wm + mi * 16;
                ah[mi][0] = pack_h2(*(const float2*)&sA[(r + g) * SROW + k0 + 2 * tg]);
                ah[mi][1] = pack_h2(*(const float2*)&sA[(r + g + 8) * SROW + k0 + 2 * tg]);
                ah[mi][2] = pack_h2(*(const float2*)&sA[(r + g) * SROW + k0 + 8 + 2 * tg]);
                ah[mi][3] = pack_h2(*(const float2*)&sA[(r + g + 8) * SROW + k0 + 8 + 2 * tg]);
            }
#pragma unroll
            for (int ni = 0; ni < NI; ni++) {
                int cb = wn + ni * 8;
                unsigned b0 = pack_h2(*(const float2*)&sB[(cb + g) * SROW + k0 + 2 * tg]);
                unsigned b1 = pack_h2(*(const float2*)&sB[(cb + g) * SROW + k0 + 8 + 2 * tg]);
#pragma unroll
                for (int mi = 0; mi < 2; mi++) MMA_F16(acc[mi][ni], ah[mi], b0, b1);
            }
        }
        __syncthreads();
    }

#pragma unroll
    for (int mi = 0; mi < 2; mi++) {
#pragma unroll
        for (int ni = 0; ni < NI; ni++) {
            int r0 = m0 + wm + mi * 16 + g;
            int c0 = n0 + wn + ni * 8 + tg * 2;
#pragma unroll
            for (int half = 0; half < 2; half++) {
                int rr = r0 + half * 8;
#pragma unroll
                for (int j = 0; j < 2; j++) {
                    int cc = c0 + j;
                    if (cc >= N) continue;
                    float v = acc[mi][ni][half * 2 + j];
                    if (final_z) {
                        if (bias) v += bias[cc];
                        if (Csrc) v += Csrc[(size_t)rr * ldsrc + cc];
                    }
                    C[(size_t)rr * ldc + cc] = (OutT)v;
                }
            }
        }
    }
}

// ---------------- small kernels ----------------
__global__ void bsum_kernel(float* __restrict__ out, const float* __restrict__ a,
                            const float* __restrict__ b) {
    int i = blockIdx.x * blockDim.x + threadIdx.x;
    if (i < 2048) out[i] = a[i] + b[i];
}

__global__ void gather_kernel(const int* __restrict__ cap, const float* __restrict__ table,
                              float* __restrict__ E) {
    int bt = blockIdx.x;
    int b = bt / TSTEPS, tt = bt % TSTEPS;
    int idx = cap[b * (TSTEPS + 1) + tt];
    const float4* src = (const float4*)(table + (size_t)idx * EMBD);
    float4* dst = (float4*)(E + (size_t)bt * EMBD);
    dst[threadIdx.x] = src[threadIdx.x];
}

// single pass over enc: compute mean AND write fp16 mirror
__global__ void prep_enc_kernel(const float* __restrict__ enc, __half* __restrict__ ench,
                                float* __restrict__ mean) {
    int b = blockIdx.y;
    int e = blockIdx.x * 256 + threadIdx.x;   // 8x256 = 2048
    const float* ep = enc + (size_t)b * RR * ENCD + e;
    __half* op = ench + (size_t)b * RR * ENCD + e;
    float acc = 0.f;
#pragma unroll 4
    for (int r = 0; r < RR; r++) {
        float v = ep[(size_t)r * ENCD];
        acc += v;
        op[(size_t)r * ENCD] = __float2half_rn(v);
    }
    mean[b * ENCD + e] = acc * (1.f / (float)RR);
}

// ============ fused attention + softmax + context + gadd (one block per b) ============
__global__ void __launch_bounds__(1024) att_ctx_kernel(
    const __half* __restrict__ att1h, const __half* __restrict__ ench,
    const float* __restrict__ hproj,
    const float* __restrict__ wfull, const float* __restrict__ bfull,
    const float* __restrict__ embproj,
    float* __restrict__ ctx, float* __restrict__ gadd,
    float* __restrict__ out_alpha, int t) {
    int b = blockIdx.x;
    int tid = threadIdx.x;  // 1024
    int warp = tid >> 5, lane = tid & 31;
    __shared__ float s_att2[512], s_wf[512], s_sc[RR], s_red[32];
    __shared__ float s_part[4][2048];
    if (tid < 512) {
        s_att2[tid] = hproj[b * 4608 + tid];
        s_wf[tid] = wfull[tid];
    }
    __syncthreads();

    // scores: warp per r, float4 (8 halves) loads — 2 per row per lane
    float bf = bfull[0];
    for (int r = warp; r < RR; r += 32) {
        const float4* ap = (const float4*)(att1h + (size_t)(b * RR + r) * ATTD);
        float s = 0.f;
#pragma unroll
        for (int i = 0; i < 2; i++) {
            float4 v = ap[lane + i * 32];
            const __half2* hv = (const __half2*)&v;
            int a = (lane + i * 32) * 8;
#pragma unroll
            for (int j = 0; j < 4; j++) {
                float2 f = __half22float2(hv[j]);
                s += fmaxf(f.x + s_att2[a + 2 * j], 0.f) * s_wf[a + 2 * j]
                   + fmaxf(f.y + s_att2[a + 2 * j + 1], 0.f) * s_wf[a + 2 * j + 1];
            }
        }
#pragma unroll
        for (int o = 16; o; o >>= 1) s += __shfl_xor_sync(0xffffffffu, s, o);
        if (lane == 0) s_sc[r] = s + bf;
    }
    __syncthreads();

    // softmax
    float m = -1e30f;
    if (tid < RR) m = s_sc[tid];
#pragma unroll
    for (int o = 16; o; o >>= 1) m = fmaxf(m, __shfl_xor_sync(0xffffffffu, m, o));
    if (lane == 0) s_red[warp] = m;
    __syncthreads();
    m = s_red[0];
#pragma unroll
    for (int w = 1; w < 32; w++) m = fmaxf(m, s_red[w]);
    __syncthreads();
    float sum = 0.f;
    if (tid < RR) {
        float e = expf(s_sc[tid] - m);
        s_sc[tid] = e;
        sum = e;
    }
#pragma unroll
    for (int o = 16; o; o >>= 1) sum += __shfl_xor_sync(0xffffffffu, sum, o);
    if (lane == 0) s_red[warp] = sum;
    __syncthreads();
    sum = 0.f;
#pragma unroll
    for (int w = 0; w < 32; w++) sum += s_red[w];
    float inv = 1.f / sum;
    if (tid < RR) out_alpha[((size_t)b * TSTEPS + t) * RR + tid] = s_sc[tid] * inv;
    __syncthreads();

    // context: 4 row-groups x 256 e-threads, float4 (8 halves) per row
    {
        int rg = tid >> 8;       // 0..3
        int et = tid & 255;      // 0..255  (8 halves each => 2048)
        const float4* ep4 = (const float4*)(ench + (size_t)b * RR * ENCD) + et;
        float a8[8];
#pragma unroll
        for (int j = 0; j < 8; j++) a8[j] = 0.f;
#pragma unroll 4
        for (int r = rg; r < RR; r += 4) {
            float4 v = ep4[(size_t)r * 256];
            const __half2* hv = (const __half2*)&v;
            float a = s_sc[r];
#pragma unroll
            for (int j = 0; j < 4; j++) {
                float2 f = __half22float2(hv[j]);
                a8[2 * j] += a * f.x;
                a8[2 * j + 1] += a * f.y;
            }
        }
#pragma unroll
        for (int j = 0; j < 8; j++) s_part[rg][et * 8 + j] = a8[j];
    }
    __syncthreads();

#pragma unroll
    for (int j = 0; j < 2; j++) {
        int e = tid * 2 + j;
        float v = (s_part[0][e] + s_part[1][e]) + (s_part[2][e] + s_part[3][e]);
        v *= inv;
        float gp = hproj[b * 4608 + 512 + e];
        ctx[b * ENCD + e] = v / (1.f + expf(-gp));
        gadd[b * 2048 + e] = embproj[((size_t)b * TSTEPS + t) * 2048 + e]
                           + hproj[b * 4608 + 2560 + e];
    }
}

// sums 4 split-K partials + gadd, LSTM pointwise, writes h to state AND g_H[t]
__global__ void lstm_kernel(const float* __restrict__ gpart, const float* __restrict__ gadd,
                            float* __restrict__ state, float* __restrict__ Hout, int t) {
    int b = blockIdx.x, d = threadIdx.x;  // 512 threads
    float gt[4];
#pragma unroll
    for (int q = 0; q < 4; q++) {
        int j = b * 2048 + q * 512 + d;
        float s = gadd[j];
#pragma unroll
        for (int z = 0; z < 4; z++) s += gpart[z * BATCH * 2048 + j];
        gt[q] = s;
    }
    float i_ = 1.f / (1.f + expf(-gt[0]));
    float f_ = 1.f / (1.f + expf(-gt[1]));
    float g_ = tanhf(gt[2]);
    float o_ = 1.f / (1.f + expf(-gt[3]));
    float c = state[b * 1024 + 512 + d];
    float cn = f_ * c + i_ * g_;
    float hn = o_ * tanhf(cn);
    state[b * 1024 + d] = hn;
    state[b * 1024 + 512 + d] = cn;
    Hout[((size_t)b * TSTEPS + t) * DECD + d] = hn;
}

// ---------------- host ----------------
static float* symaddr(const void* sym) {
    void* p = nullptr;
    cudaGetSymbolAddress(&p, sym);
    return (float*)p;
}

static const int SMEM64 = 2 * (192 * SROW) * 4;    // 55296
static const int SMEM128 = 2 * (256 * SROW) * 4;   // 73728

template <int BN, typename OutT>
static void launch_f16(const float* A, int lda, const float* B, int ldb,
                       const float* bias, const float* Csrc, int ldsrc,
                       OutT* C, int ldc, size_t zstride,
                       int M, int N, int K, int zsplit) {
    dim3 grid((N + BN - 1) / BN, M / 128, zsplit);
    int smem = (BN == 64) ? SMEM64 : SMEM128;
    gemm_f16<BN, OutT><<<grid, 256, smem>>>(A, lda, B, ldb, bias, Csrc, ldsrc, C, ldc,
                                            zstride, N, K / zsplit);
}

extern "C" void kernel_launch(void* const* d_in, const int* in_sizes, int n_in,
                              void* d_out, int out_size) {
    const float* enc       = (const float*)d_in[0];
    const int*   captions  = (const int*)d_in[1];
    const float* W_enc_att = (const float*)d_in[2];
    const float* b_enc_att = (const float*)d_in[3];
    const float* W_dec_att = (const float*)d_in[4];
    const float* b_dec_att = (const float*)d_in[5];
    const float* W_full    = (const float*)d_in[6];
    const float* b_full    = (const float*)d_in[7];
    const float* emb_table = (const float*)d_in[8];
    const float* W_ih      = (const float*)d_in[9];
    const float* W_hh      = (const float*)d_in[10];
    const float* b_ih      = (const float*)d_in[11];
    const float* b_hh      = (const float*)d_in[12];
    const float* W_init_h  = (const float*)d_in[13];
    const float* b_init_h  = (const float*)d_in[14];
    const float* W_init_c  = (const float*)d_in[15];
    const float* b_init_c  = (const float*)d_in[16];
    const float* W_fbeta   = (const float*)d_in[17];
    const float* b_fbeta   = (const float*)d_in[18];
    const float* W_fc      = (const float*)d_in[19];
    const float* b_fc      = (const float*)d_in[20];

    float* out_pred  = (float*)d_out;
    float* out_alpha = out_pred + (size_t)BATCH * TSTEPS * VOC;

    __half* att1h = (__half*)symaddr(g_att1h);
    __half* ench  = (__half*)symaddr(g_ench);
    float* meanb  = symaddr(g_mean);
    float* state  = symaddr(g_state);
    float* hproj  = symaddr(g_hproj);
    float* ctx    = symaddr(g_ctx);
    float* gadd   = symaddr(g_gadd);
    float* gpart  = symaddr(g_gpart);
    float* Hbuf   = symaddr(g_H);
    float* E      = symaddr(g_E);
    float* embprj = symaddr(g_embproj);
    float* Wcat   = symaddr(g_Wcat);
    float* bcat   = symaddr(g_bcat);
    float* bsum   = symaddr(g_bsum);
    float* Winit  = symaddr(g_Winit);
    float* binit  = symaddr(g_binit);

    cudaFuncSetAttribute(gemm_f16<64, float>, cudaFuncAttributeMaxDynamicSharedMemorySize, SMEM64);
    cudaFuncSetAttribute(gemm_f16<128, float>, cudaFuncAttributeMaxDynamicSharedMemorySize, SMEM128);
    cudaFuncSetAttribute(gemm_f16<128, __half>, cudaFuncAttributeMaxDynamicSharedMemorySize, SMEM128);

    // ---- prologue: weight concats ----
    cudaMemcpyAsync(Wcat, W_dec_att, (size_t)512 * 512 * 4, cudaMemcpyDeviceToDevice, 0);
    cudaMemcpyAsync(Wcat + 512 * 512, W_fbeta, (size_t)2048 * 512 * 4, cudaMemcpyDeviceToDevice, 0);
    cudaMemcpyAsync(Wcat + 2560 * 512, W_hh, (size_t)2048 * 512 * 4, cudaMemcpyDeviceToDevice, 0);
    cudaMemcpyAsync(bcat, b_dec_att, 512 * 4, cudaMemcpyDeviceToDevice, 0);
    cudaMemcpyAsync(bcat + 512, b_fbeta, 2048 * 4, cudaMemcpyDeviceToDevice, 0);
    cudaMemsetAsync(bcat + 2560, 0, 2048 * 4, 0);
    cudaMemcpyAsync(Winit, W_init_h, (size_t)512 * 2048 * 4, cudaMemcpyDeviceToDevice, 0);
    cudaMemcpyAsync(Winit + (size_t)512 * 2048, W_init_c, (size_t)512 * 2048 * 4,
                    cudaMemcpyDeviceToDevice, 0);
    cudaMemcpyAsync(binit, b_init_h, 512 * 4, cudaMemcpyDeviceToDevice, 0);
    cudaMemcpyAsync(binit + 512, b_init_c, 512 * 4, cudaMemcpyDeviceToDevice, 0);

    bsum_kernel<<<8, 256>>>(bsum, b_ih, b_hh);
    // one pass over enc: mean + fp16 mirror
    prep_enc_kernel<<<dim3(8, BATCH), 256>>>(enc, ench, meanb);
    // state = mean @ [W_init_h; W_init_c]^T + [b_init_h; b_init_c]
    launch_f16<64, float>(meanb, ENCD, Winit, ENCD, binit, nullptr, 0, state, 1024, 0,
                          BATCH, 1024, ENCD, 1);
    gather_kernel<<<BATCH * TSTEPS, 128>>>(captions, emb_table, E);
    // embproj (all t): E @ W_ih[:, :512]^T + (b_ih + b_hh)
    launch_f16<128, float>(E, EMBD, W_ih, EMBD + ENCD, bsum, nullptr, 0, embprj, 2048, 0,
                           BATCH * TSTEPS, 2048, EMBD, 1);
    // att1 = enc @ W_enc_att^T + b_enc_att (fp16 output) — BN=128 halves enc re-streaming
    launch_f16<128, __half>(enc, ENCD, W_enc_att, ENCD, b_enc_att, nullptr, 0, att1h, ATTD, 0,
                            BATCH * RR, ATTD, ENCD, 1);

    // ---- recurrence (fc hoisted) ----
    for (int t = 0; t < TSTEPS; t++) {
        // hproj = h @ [W_dec_att; W_fbeta; W_hh]^T + [b_dec_att; b_fbeta; 0]
        launch_f16<64, float>(state, 1024, Wcat, 512, bcat, nullptr, 0, hproj, 4608, 0,
                              BATCH, 4608, DECD, 1);
        att_ctx_kernel<<<BATCH, 1024>>>(att1h, ench, hproj, W_full, b_full, embprj,
                                        ctx, gadd, out_alpha, t);
        // gates partials = ctx @ W_ih[:, 512:]^T   (split-K = 4)
        launch_f16<64, float>(ctx, ENCD, W_ih + 512, EMBD + ENCD, nullptr, nullptr, 0, gpart,
                              2048, (size_t)BATCH * 2048, BATCH, 2048, ENCD, 4);
        lstm_kernel<<<BATCH, 512>>>(gpart, gadd, state, Hbuf, t);
    }

    // ---- batched fc: preds[b,t,:] = h_t @ W_fc^T + b_fc — BN=128 halves H re-reads ----
    launch_f16<128, float>(Hbuf, DECD, W_fc, DECD, b_fc, nullptr, 0, out_pred, VOC, 0,
                           BATCH * TSTEPS, VOC, DECD, 1);
}